// round 2
// baseline (speedup 1.0000x reference)
#include <cuda_runtime.h>

#define CB 4
#define CN 2048
#define CD 256
#define CE 3
#define CH 2
#define CDK 128
#define NEGF -1000000000.0f

// ---- scratch (static device globals; no allocation allowed) ----
__device__ float g_q[(size_t)CE*CB*CN*CD];     // per-edge Q projections
__device__ float g_k[(size_t)CE*CB*CN*CD];     // per-edge K projections
__device__ float g_h1[(size_t)CB*CN*CD];       // GCN h1 buffer
__device__ float g_x0[(size_t)CB*CN*CD];       // head-0 node state
__device__ float g_x1[(size_t)CB*CN*CD];       // head-1 node state
__device__ float g_degs[(size_t)CH*CB*CN];     // row sums of attn (degs)

// =====================================================================
// Generic GEMM: C[M,256] = A[M,K] @ W[K,256] (+bias).
// A may be split across two buffers (A0 covers k<256, A1 covers k>=256),
// each with row stride 256 — used by the final concat @ agg_W.
// Tiles: BM=BN=64, BK=16, 256 threads, 4x4 per thread.
// =====================================================================
__global__ void __launch_bounds__(256) gemm_xw_kernel(
    const float* __restrict__ A0, const float* __restrict__ A1,
    const float* __restrict__ W, const float* __restrict__ bias,
    float* __restrict__ C, int K)
{
    __shared__ float As[16][64];
    __shared__ float Ws[16][64];
    const int tid = threadIdx.x;
    const int bm = blockIdx.x * 64;
    const int bn = blockIdx.y * 64;
    const int tx = tid & 15;
    const int ty = tid >> 4;
    const int lm = tid >> 2;
    const int lk = (tid & 3) * 4;
    const int wk = tid >> 4;
    const int wn = (tid & 15) * 4;
    float acc[4][4] = {};
    for (int k0 = 0; k0 < K; k0 += 16) {
        int gk = k0 + lk;
        const float* Ap = (gk < 256) ? (A0 + (size_t)(bm + lm) * 256 + gk)
                                     : (A1 + (size_t)(bm + lm) * 256 + (gk - 256));
        float4 av = *(const float4*)Ap;
        As[lk+0][lm] = av.x; As[lk+1][lm] = av.y;
        As[lk+2][lm] = av.z; As[lk+3][lm] = av.w;
        *(float4*)&Ws[wk][wn] = *(const float4*)(W + (size_t)(k0 + wk) * 256 + bn + wn);
        __syncthreads();
        #pragma unroll
        for (int k = 0; k < 16; k++) {
            float a[4], b[4];
            *(float4*)a = *(const float4*)&As[k][ty*4];
            *(float4*)b = *(const float4*)&Ws[k][tx*4];
            #pragma unroll
            for (int i = 0; i < 4; i++)
                #pragma unroll
                for (int j = 0; j < 4; j++)
                    acc[i][j] = fmaf(a[i], b[j], acc[i][j]);
        }
        __syncthreads();
    }
    #pragma unroll
    for (int i = 0; i < 4; i++) {
        int gm = bm + ty*4 + i;
        #pragma unroll
        for (int j = 0; j < 4; j++) {
            int gn = bn + tx*4 + j;
            float bv = bias ? bias[gn] : 0.0f;
            C[(size_t)gm*256 + gn] = acc[i][j] + bv;
        }
    }
}

// =====================================================================
// Edge-typed attention scores. For a 64x64 (n,m) tile of one (b,h):
// compute QKt for ALL 3 edges with register blocking, then select by
// adj[b,n,m] and apply the NEG mask. Writes directly into the
// graph_attention output region laid out (H,B,N,N).
// =====================================================================
__global__ void __launch_bounds__(256) scores_kernel(
    const int* __restrict__ adj, float* __restrict__ ga)
{
    __shared__ float Qs[CE][16][64];
    __shared__ float Ks[CE][16][64];
    const int tid = threadIdx.x;
    const int bh = blockIdx.z;
    const int b = bh >> 1;
    const int h = bh & 1;
    const int m0 = blockIdx.x * 64;
    const int n0 = blockIdx.y * 64;
    const int tx = tid & 15;
    const int ty = tid >> 4;
    const int lr = tid >> 2;
    const int lk = (tid & 3) * 4;
    float acc[CE][4][4] = {};
    for (int k0 = 0; k0 < CDK; k0 += 16) {
        #pragma unroll
        for (int e = 0; e < CE; e++) {
            const float* qp = g_q + ((size_t)(e*CB + b)*CN + (n0 + lr))*CD + h*CDK + k0 + lk;
            float4 qv = *(const float4*)qp;
            Qs[e][lk+0][lr]=qv.x; Qs[e][lk+1][lr]=qv.y;
            Qs[e][lk+2][lr]=qv.z; Qs[e][lk+3][lr]=qv.w;
            const float* kp = g_k + ((size_t)(e*CB + b)*CN + (m0 + lr))*CD + h*CDK + k0 + lk;
            float4 kv = *(const float4*)kp;
            Ks[e][lk+0][lr]=kv.x; Ks[e][lk+1][lr]=kv.y;
            Ks[e][lk+2][lr]=kv.z; Ks[e][lk+3][lr]=kv.w;
        }
        __syncthreads();
        #pragma unroll
        for (int k = 0; k < 16; k++) {
            #pragma unroll
            for (int e = 0; e < CE; e++) {
                float qa[4], kb[4];
                *(float4*)qa = *(const float4*)&Qs[e][k][ty*4];
                *(float4*)kb = *(const float4*)&Ks[e][k][tx*4];
                #pragma unroll
                for (int i = 0; i < 4; i++)
                    #pragma unroll
                    for (int j = 0; j < 4; j++)
                        acc[e][i][j] = fmaf(qa[i], kb[j], acc[e][i][j]);
            }
        }
        __syncthreads();
    }
    const float scale = 0.088388347648318447f;  // 1/sqrt(128)
    float* gout = ga + ((size_t)(h*CB + b)*CN)*CN;
    const int* adjb = adj + (size_t)b*CN*CN;
    #pragma unroll
    for (int i = 0; i < 4; i++) {
        int n = n0 + ty*4 + i;
        #pragma unroll
        for (int j = 0; j < 4; j++) {
            int m = m0 + tx*4 + j;
            int t = adjb[(size_t)n*CN + m];
            float raw = 0.0f;
            if (t == 1)      raw = acc[0][i][j]*scale;
            else if (t == 2) raw = acc[1][i][j]*scale;
            else if (t == 3) raw = acc[2][i][j]*scale;
            gout[(size_t)n*CN + m] = (raw == 0.0f) ? NEGF : raw;
        }
    }
}

// =====================================================================
// Row softmax over 2048 (row cached in registers, single exp per elem),
// in-place on the graph_attention region; also emits degs = row sum of
// the normalized attention (matching reference numerics within 1 ulp-ish).
// =====================================================================
__global__ void __launch_bounds__(256) softmax_kernel(
    float* __restrict__ ga, float* __restrict__ degs)
{
    float* p = ga + ((size_t)blockIdx.y * CN + blockIdx.x) * CN;
    const int tid = threadIdx.x;
    float v[8];
    #pragma unroll
    for (int i = 0; i < 8; i++) v[i] = p[tid + 256*i];
    float lmax = v[0];
    #pragma unroll
    for (int i = 1; i < 8; i++) lmax = fmaxf(lmax, v[i]);
    #pragma unroll
    for (int o = 16; o; o >>= 1) lmax = fmaxf(lmax, __shfl_xor_sync(0xffffffffu, lmax, o));
    __shared__ float red[8];
    if ((tid & 31) == 0) red[tid >> 5] = lmax;
    __syncthreads();
    float rmax = red[0];
    #pragma unroll
    for (int i = 1; i < 8; i++) rmax = fmaxf(rmax, red[i]);
    float lsum = 0.0f;
    #pragma unroll
    for (int i = 0; i < 8; i++) { v[i] = __expf(v[i] - rmax); lsum += v[i]; }
    #pragma unroll
    for (int o = 16; o; o >>= 1) lsum += __shfl_xor_sync(0xffffffffu, lsum, o);
    __syncthreads();
    __shared__ float red2[8];
    if ((tid & 31) == 0) red2[tid >> 5] = lsum;
    __syncthreads();
    float rsum = 0.0f;
    #pragma unroll
    for (int i = 0; i < 8; i++) rsum += red2[i];
    float rinv = 1.0f / rsum;
    float lw = 0.0f;
    #pragma unroll
    for (int i = 0; i < 8; i++) { float w = v[i]*rinv; p[tid + 256*i] = w; lw += w; }
    #pragma unroll
    for (int o = 16; o; o >>= 1) lw += __shfl_xor_sync(0xffffffffu, lw, o);
    __shared__ float red3[8];
    if ((tid & 31) == 0) red3[tid >> 5] = lw;
    __syncthreads();
    if (tid == 0) {
        float s = 0.0f;
        #pragma unroll
        for (int i = 0; i < 8; i++) s += red3[i];
        degs[(size_t)blockIdx.y*CN + blockIdx.x] = s;
    }
}

// =====================================================================
// GCN aggregation: C = attn(h,b) @ h1(b), fused epilogue
// x_out = x_old + relu(C/deg + gcn_b). 128x128x16 tiles, 8x8 per thread.
// blockIdx.z enumerates hb = h*B + b starting at hb0 (so one launch can
// cover both heads when they share h1, i.e. iteration 0).
// =====================================================================
__global__ void __launch_bounds__(256) spmm_kernel(
    const float* __restrict__ ga,
    const float* __restrict__ xoldA, const float* __restrict__ xoldB,
    float* __restrict__ xoutA, float* __restrict__ xoutB,
    const float* __restrict__ bias, int hb0)
{
    __shared__ float As[16][128];
    __shared__ float Hs[16][128];
    const int tid = threadIdx.x;
    const int hb = hb0 + blockIdx.z;
    const int h = hb / CB;
    const int b = hb % CB;
    const int f0 = blockIdx.x * 128;
    const int n0 = blockIdx.y * 128;
    const int tx = tid & 15;
    const int ty = tid >> 4;
    const float* Ab = ga + (size_t)hb*CN*CN;
    const float* Hb = g_h1 + (size_t)b*CN*CD;
    const int ar = tid >> 1;
    const int ak = (tid & 1) * 8;
    const int hk = tid >> 4;
    const int hf = (tid & 15) * 8;
    float acc[8][8] = {};
    for (int k0 = 0; k0 < CN; k0 += 16) {
        const float* ap = Ab + (size_t)(n0 + ar)*CN + k0 + ak;
        float4 a0 = *(const float4*)ap;
        float4 a1 = *(const float4*)(ap + 4);
        As[ak+0][ar]=a0.x; As[ak+1][ar]=a0.y; As[ak+2][ar]=a0.z; As[ak+3][ar]=a0.w;
        As[ak+4][ar]=a1.x; As[ak+5][ar]=a1.y; As[ak+6][ar]=a1.z; As[ak+7][ar]=a1.w;
        const float* hp = Hb + (size_t)(k0 + hk)*CD + f0 + hf;
        *(float4*)&Hs[hk][hf]     = *(const float4*)hp;
        *(float4*)&Hs[hk][hf + 4] = *(const float4*)(hp + 4);
        __syncthreads();
        #pragma unroll
        for (int k = 0; k < 16; k++) {
            float a[8], hv[8];
            *(float4*)&a[0]  = *(const float4*)&As[k][ty*8];
            *(float4*)&a[4]  = *(const float4*)&As[k][ty*8 + 4];
            *(float4*)&hv[0] = *(const float4*)&Hs[k][tx*8];
            *(float4*)&hv[4] = *(const float4*)&Hs[k][tx*8 + 4];
            #pragma unroll
            for (int i = 0; i < 8; i++)
                #pragma unroll
                for (int j = 0; j < 8; j++)
                    acc[i][j] = fmaf(a[i], hv[j], acc[i][j]);
        }
        __syncthreads();
    }
    const float* xold = (h == 0) ? xoldA : xoldB;
    float* xout = (h == 0) ? xoutA : xoutB;
    const float* degp = g_degs + (size_t)hb*CN;
    #pragma unroll
    for (int i = 0; i < 8; i++) {
        int n = n0 + ty*8 + i;
        float dinv = 1.0f / degp[n];
        #pragma unroll
        for (int j = 0; j < 8; j++) {
            int f = f0 + tx*8 + j;
            size_t idx = (size_t)b*CN*CD + (size_t)n*CD + f;
            float v = acc[i][j]*dinv + bias[f];
            xout[idx] = xold[idx] + fmaxf(v, 0.0f);
        }
    }
}

// =====================================================================
extern "C" void kernel_launch(void* const* d_in, const int* in_sizes, int n_in,
                              void* d_out, int out_size)
{
    (void)in_sizes; (void)n_in; (void)out_size;
    const float* X   = (const float*)d_in[0];
    const int*   adj = (const int*)d_in[1];
    const float* Wq  = (const float*)d_in[2];
    const float* bq  = (const float*)d_in[3];
    const float* Wk  = (const float*)d_in[4];
    const float* bk  = (const float*)d_in[5];
    const float* gW  = (const float*)d_in[6];
    const float* gb  = (const float*)d_in[7];
    const float* aW  = (const float*)d_in[8];
    const float* ab  = (const float*)d_in[9];

    float* out = (float*)d_out;                      // (B,N,D)
    float* ga  = out + (size_t)CB*CN*CD;             // (H,B,N,N)

    float *qb, *kb, *h1, *x0, *x1, *dg;
    cudaGetSymbolAddress((void**)&qb, g_q);
    cudaGetSymbolAddress((void**)&kb, g_k);
    cudaGetSymbolAddress((void**)&h1, g_h1);
    cudaGetSymbolAddress((void**)&x0, g_x0);
    cudaGetSymbolAddress((void**)&x1, g_x1);
    cudaGetSymbolAddress((void**)&dg, g_degs);

    const dim3 gproj(CB*CN/64, CD/64);               // 128 x 4

    // Q/K projections for each edge type
    for (int e = 0; e < CE; e++) {
        gemm_xw_kernel<<<gproj, 256>>>(X, nullptr, Wq + (size_t)e*CD*CD, bq + e*CD,
                                       qb + (size_t)e*CB*CN*CD, CD);
        gemm_xw_kernel<<<gproj, 256>>>(X, nullptr, Wk + (size_t)e*CD*CD, bk + e*CD,
                                       kb + (size_t)e*CB*CN*CD, CD);
    }

    // Edge-typed scores -> graph_attention region, then softmax (+degs)
    scores_kernel<<<dim3(CN/64, CN/64, CB*CH), 256>>>(adj, ga);
    softmax_kernel<<<dim3(CN, CH*CB), 256>>>(ga, dg);

    // GCN iteration 0: h1 = X @ gcn_W[0] (shared by both heads)
    gemm_xw_kernel<<<gproj, 256>>>(X, nullptr, gW, nullptr, h1, CD);
    spmm_kernel<<<dim3(CD/128, CN/128, CH*CB), 256>>>(ga, X, X, x0, x1, gb, 0);

    // GCN iteration 1, head 0
    gemm_xw_kernel<<<gproj, 256>>>(x0, nullptr, gW + (size_t)CD*CD, nullptr, h1, CD);
    spmm_kernel<<<dim3(CD/128, CN/128, CB), 256>>>(ga, x0, x0, x0, x0, gb + CD, 0);

    // GCN iteration 1, head 1
    gemm_xw_kernel<<<gproj, 256>>>(x1, nullptr, gW + (size_t)CD*CD, nullptr, h1, CD);
    spmm_kernel<<<dim3(CD/128, CN/128, CB), 256>>>(ga, x1, x1, x1, x1, gb + CD, 4);

    // Aggregation: out = concat(x0, x1) @ agg_W + agg_b
    gemm_xw_kernel<<<gproj, 256>>>(x0, x1, aW, ab, out, 2*CD);
}

// round 6
// speedup vs baseline: 1.1879x; 1.1879x over previous
#include <cuda_runtime.h>
#include <cstdint>

#define CB 4
#define CN 2048
#define CD 256
#define CE 3
#define CH 2
#define CDK 128
#define NEGF -1000000000.0f

// ---- scratch (static device globals; no allocation allowed) ----
__device__ float g_q[(size_t)CE*CB*CN*CD];     // per-edge Q projections
__device__ float g_k[(size_t)CE*CB*CN*CD];     // per-edge K projections
__device__ float g_h1[(size_t)CB*CN*CD];       // GCN h1 buffer
__device__ float g_x0[(size_t)CB*CN*CD];       // head-0 node state
__device__ float g_x1[(size_t)CB*CN*CD];       // head-1 node state
__device__ float g_degs[(size_t)CH*CB*CN];     // row sums of attn (degs)

// ---------------------------------------------------------------------
// tf32 MMA helpers: m16n8k8, row.col, fp32 accumulate.
// Split-precision: x = hi + lo with hi = top-10-mantissa-bits(x);
// x*y ~= hi_x*hi_y + hi_x*lo_y + lo_x*hi_y  (3 MMAs, ~2^-21 rel err)
// ---------------------------------------------------------------------
__device__ __forceinline__ float tf32_hi(float x) {
    return __uint_as_float(__float_as_uint(x) & 0xFFFFE000u);
}

__device__ __forceinline__ void mma_tf32(float* c, const float* a, const float* b) {
    asm volatile(
        "mma.sync.aligned.m16n8k8.row.col.f32.tf32.tf32.f32 "
        "{%0,%1,%2,%3}, {%4,%5,%6,%7}, {%8,%9}, {%0,%1,%2,%3};\n"
        : "+f"(c[0]), "+f"(c[1]), "+f"(c[2]), "+f"(c[3])
        : "r"(__float_as_uint(a[0])), "r"(__float_as_uint(a[1])),
          "r"(__float_as_uint(a[2])), "r"(__float_as_uint(a[3])),
          "r"(__float_as_uint(b[0])), "r"(__float_as_uint(b[1])));
}

// =====================================================================
// Generic GEMM (FFMA): C[M,256] = A[M,K] @ W[K,256] (+bias).
// =====================================================================
__global__ void __launch_bounds__(256) gemm_xw_kernel(
    const float* __restrict__ A0, const float* __restrict__ A1,
    const float* __restrict__ W, const float* __restrict__ bias,
    float* __restrict__ C, int K)
{
    __shared__ float As[16][64];
    __shared__ float Ws[16][64];
    const int tid = threadIdx.x;
    const int bm = blockIdx.x * 64;
    const int bn = blockIdx.y * 64;
    const int tx = tid & 15;
    const int ty = tid >> 4;
    const int lm = tid >> 2;
    const int lk = (tid & 3) * 4;
    const int wk = tid >> 4;
    const int wn = (tid & 15) * 4;
    float acc[4][4] = {};
    for (int k0 = 0; k0 < K; k0 += 16) {
        int gk = k0 + lk;
        const float* Ap = (gk < 256) ? (A0 + (size_t)(bm + lm) * 256 + gk)
                                     : (A1 + (size_t)(bm + lm) * 256 + (gk - 256));
        float4 av = *(const float4*)Ap;
        As[lk+0][lm] = av.x; As[lk+1][lm] = av.y;
        As[lk+2][lm] = av.z; As[lk+3][lm] = av.w;
        *(float4*)&Ws[wk][wn] = *(const float4*)(W + (size_t)(k0 + wk) * 256 + bn + wn);
        __syncthreads();
        #pragma unroll
        for (int k = 0; k < 16; k++) {
            float a[4], b[4];
            *(float4*)a = *(const float4*)&As[k][ty*4];
            *(float4*)b = *(const float4*)&Ws[k][tx*4];
            #pragma unroll
            for (int i = 0; i < 4; i++)
                #pragma unroll
                for (int j = 0; j < 4; j++)
                    acc[i][j] = fmaf(a[i], b[j], acc[i][j]);
        }
        __syncthreads();
    }
    #pragma unroll
    for (int i = 0; i < 4; i++) {
        int gm = bm + ty*4 + i;
        #pragma unroll
        for (int j = 0; j < 4; j++) {
            int gn = bn + tx*4 + j;
            float bv = bias ? bias[gn] : 0.0f;
            C[(size_t)gm*256 + gn] = acc[i][j] + bv;
        }
    }
}

// =====================================================================
// Edge-typed attention scores (tensor-core tf32-split).
// Block tile: 128(n) x 64(m) for one (b,h); 8 warps of 32x32.
// SMEM: n-major rows of 16 k-values padded to 20 (conflict-free frag reads).
// =====================================================================
#define QK_PAD 20
__global__ void __launch_bounds__(256) scores_kernel(
    const int* __restrict__ adj, float* __restrict__ ga)
{
    __shared__ float Qs[CE][128][QK_PAD];
    __shared__ float Ks[CE][64][QK_PAD];
    const int tid = threadIdx.x;
    const int wid = tid >> 5;
    const int lane = tid & 31;
    const int g = lane >> 2;
    const int t = lane & 3;
    const int n_off = (wid & 3) * 32;
    const int m_off = (wid >> 2) * 32;
    const int bh = blockIdx.z;
    const int b = bh >> 1;
    const int h = bh & 1;
    const int m0 = blockIdx.x * 64;
    const int n0 = blockIdx.y * 128;

    float acc[CE][2][4][4];
    #pragma unroll
    for (int e = 0; e < CE; e++)
        #pragma unroll
        for (int i = 0; i < 2; i++)
            #pragma unroll
            for (int j = 0; j < 4; j++)
                #pragma unroll
                for (int c = 0; c < 4; c++) acc[e][i][j][c] = 0.0f;

    for (int kc = 0; kc < CDK; kc += 16) {
        #pragma unroll
        for (int it = 0; it < 6; it++) {          // Q tiles
            int id = tid + it * 256;
            int k4 = id & 3;
            int n  = (id >> 2) & 127;
            int e  = id >> 9;
            float4 v = *(const float4*)(g_q + ((size_t)(e*CB + b)*CN + n0 + n)*CD
                                            + h*CDK + kc + k4*4);
            *(float4*)&Qs[e][n][k4*4] = v;
        }
        #pragma unroll
        for (int it = 0; it < 3; it++) {          // K tiles
            int id = tid + it * 256;
            int k4 = id & 3;
            int m  = (id >> 2) & 63;
            int e  = id >> 8;
            float4 v = *(const float4*)(g_k + ((size_t)(e*CB + b)*CN + m0 + m)*CD
                                            + h*CDK + kc + k4*4);
            *(float4*)&Ks[e][m][k4*4] = v;
        }
        __syncthreads();
        #pragma unroll
        for (int ks = 0; ks < 16; ks += 8) {
            #pragma unroll
            for (int e = 0; e < CE; e++) {
                float ah[2][4], al[2][4];
                #pragma unroll
                for (int fn = 0; fn < 2; fn++) {
                    int r0 = n_off + fn*16 + g;
                    float a0 = Qs[e][r0    ][ks + t];
                    float a1 = Qs[e][r0 + 8][ks + t];
                    float a2 = Qs[e][r0    ][ks + t + 4];
                    float a3 = Qs[e][r0 + 8][ks + t + 4];
                    ah[fn][0]=tf32_hi(a0); al[fn][0]=a0-ah[fn][0];
                    ah[fn][1]=tf32_hi(a1); al[fn][1]=a1-ah[fn][1];
                    ah[fn][2]=tf32_hi(a2); al[fn][2]=a2-ah[fn][2];
                    ah[fn][3]=tf32_hi(a3); al[fn][3]=a3-ah[fn][3];
                }
                float bh_[4][2], bl_[4][2];
                #pragma unroll
                for (int fm = 0; fm < 4; fm++) {
                    int r = m_off + fm*8 + g;
                    float b0 = Ks[e][r][ks + t];
                    float b1 = Ks[e][r][ks + t + 4];
                    bh_[fm][0]=tf32_hi(b0); bl_[fm][0]=b0-bh_[fm][0];
                    bh_[fm][1]=tf32_hi(b1); bl_[fm][1]=b1-bh_[fm][1];
                }
                #pragma unroll
                for (int fn = 0; fn < 2; fn++)
                    #pragma unroll
                    for (int fm = 0; fm < 4; fm++) {
                        mma_tf32(acc[e][fn][fm], ah[fn], bh_[fm]);
                        mma_tf32(acc[e][fn][fm], ah[fn], bl_[fm]);
                        mma_tf32(acc[e][fn][fm], al[fn], bh_[fm]);
                    }
            }
        }
        __syncthreads();
    }

    const float scale = 0.088388347648318447f;  // 1/sqrt(128)
    float* gout = ga + (size_t)(h*CB + b)*CN*CN;
    const int* adjb = adj + (size_t)b*CN*CN;
    #pragma unroll
    for (int fn = 0; fn < 2; fn++)
        #pragma unroll
        for (int fm = 0; fm < 4; fm++)
            #pragma unroll
            for (int half = 0; half < 2; half++) {
                int n = n0 + n_off + fn*16 + g + half*8;
                int m = m0 + m_off + fm*8 + 2*t;
                int2 av = *(const int2*)&adjb[(size_t)n*CN + m];
                float2 o;
                {
                    float r = 0.0f;
                    if (av.x == 1)      r = acc[0][fn][fm][half*2]*scale;
                    else if (av.x == 2) r = acc[1][fn][fm][half*2]*scale;
                    else if (av.x == 3) r = acc[2][fn][fm][half*2]*scale;
                    o.x = (r == 0.0f) ? NEGF : r;
                }
                {
                    float r = 0.0f;
                    if (av.y == 1)      r = acc[0][fn][fm][half*2+1]*scale;
                    else if (av.y == 2) r = acc[1][fn][fm][half*2+1]*scale;
                    else if (av.y == 3) r = acc[2][fn][fm][half*2+1]*scale;
                    o.y = (r == 0.0f) ? NEGF : r;
                }
                *(float2*)&gout[(size_t)n*CN + m] = o;
            }
}

// =====================================================================
// Row softmax over 2048 + degs.
// =====================================================================
__global__ void __launch_bounds__(256) softmax_kernel(
    float* __restrict__ ga, float* __restrict__ degs)
{
    float* p = ga + ((size_t)blockIdx.y * CN + blockIdx.x) * CN;
    const int tid = threadIdx.x;
    float v[8];
    #pragma unroll
    for (int i = 0; i < 8; i++) v[i] = p[tid + 256*i];
    float lmax = v[0];
    #pragma unroll
    for (int i = 1; i < 8; i++) lmax = fmaxf(lmax, v[i]);
    #pragma unroll
    for (int o = 16; o; o >>= 1) lmax = fmaxf(lmax, __shfl_xor_sync(0xffffffffu, lmax, o));
    __shared__ float red[8];
    if ((tid & 31) == 0) red[tid >> 5] = lmax;
    __syncthreads();
    float rmax = red[0];
    #pragma unroll
    for (int i = 1; i < 8; i++) rmax = fmaxf(rmax, red[i]);
    float lsum = 0.0f;
    #pragma unroll
    for (int i = 0; i < 8; i++) { v[i] = __expf(v[i] - rmax); lsum += v[i]; }
    #pragma unroll
    for (int o = 16; o; o >>= 1) lsum += __shfl_xor_sync(0xffffffffu, lsum, o);
    __syncthreads();
    __shared__ float red2[8];
    if ((tid & 31) == 0) red2[tid >> 5] = lsum;
    __syncthreads();
    float rsum = 0.0f;
    #pragma unroll
    for (int i = 0; i < 8; i++) rsum += red2[i];
    float rinv = 1.0f / rsum;
    float lw = 0.0f;
    #pragma unroll
    for (int i = 0; i < 8; i++) { float w = v[i]*rinv; p[tid + 256*i] = w; lw += w; }
    #pragma unroll
    for (int o = 16; o; o >>= 1) lw += __shfl_xor_sync(0xffffffffu, lw, o);
    __shared__ float red3[8];
    if ((tid & 31) == 0) red3[tid >> 5] = lw;
    __syncthreads();
    if (tid == 0) {
        float s = 0.0f;
        #pragma unroll
        for (int i = 0; i < 8; i++) s += red3[i];
        degs[(size_t)blockIdx.y*CN + blockIdx.x] = s;
    }
}

// =====================================================================
// GCN aggregation (tensor-core tf32-split): C = attn(hb) @ h1(b),
// epilogue x_out = x_old + relu(C/deg + gcn_b).
// Block tile 128(n) x 128(f), 8 warps of 32x64. k-chunk 16 over 2048.
// =====================================================================
__global__ void __launch_bounds__(256, 2) spmm_kernel(
    const float* __restrict__ ga,
    const float* __restrict__ xoldA, const float* __restrict__ xoldB,
    float* __restrict__ xoutA, float* __restrict__ xoutB,
    const float* __restrict__ bias, int hb0)
{
    __shared__ float As[128][QK_PAD];
    __shared__ float Hs[16][136];
    const int tid = threadIdx.x;
    const int wid = tid >> 5;
    const int lane = tid & 31;
    const int g = lane >> 2;
    const int t = lane & 3;
    const int n_off = (wid & 3) * 32;
    const int f_off = (wid >> 2) * 64;
    const int hb = hb0 + blockIdx.z;
    const int h = hb / CB;
    const int b = hb % CB;
    const int f0 = blockIdx.x * 128;
    const int n0 = blockIdx.y * 128;
    const float* Ab = ga + (size_t)hb*CN*CN;
    const float* Hb = g_h1 + (size_t)b*CN*CD;

    float acc[2][8][4];
    #pragma unroll
    for (int i = 0; i < 2; i++)
        #pragma unroll
        for (int j = 0; j < 8; j++)
            #pragma unroll
            for (int c = 0; c < 4; c++) acc[i][j][c] = 0.0f;

    for (int kc = 0; kc < CN; kc += 16) {
        #pragma unroll
        for (int it = 0; it < 2; it++) {          // A: 128n * 4 vec
            int id = tid + it * 256;
            int k4 = id & 3;
            int n  = id >> 2;
            float4 v = *(const float4*)(Ab + (size_t)(n0 + n)*CN + kc + k4*4);
            *(float4*)&As[n][k4*4] = v;
        }
        #pragma unroll
        for (int it = 0; it < 2; it++) {          // H: 16k * 32 vec
            int id = tid + it * 256;
            int f4 = id & 31;
            int k  = id >> 5;
            float4 v = *(const float4*)(Hb + (size_t)(kc + k)*CD + f0 + f4*4);
            *(float4*)&Hs[k][f4*4] = v;
        }
        __syncthreads();
        #pragma unroll
        for (int ks = 0; ks < 16; ks += 8) {
            float ah[2][4], al[2][4];
            #pragma unroll
            for (int fn = 0; fn < 2; fn++) {
                int r0 = n_off + fn*16 + g;
                float a0 = As[r0    ][ks + t];
                float a1 = As[r0 + 8][ks + t];
                float a2 = As[r0    ][ks + t + 4];
                float a3 = As[r0 + 8][ks + t + 4];
                ah[fn][0]=tf32_hi(a0); al[fn][0]=a0-ah[fn][0];
                ah[fn][1]=tf32_hi(a1); al[fn][1]=a1-ah[fn][1];
                ah[fn][2]=tf32_hi(a2); al[fn][2]=a2-ah[fn][2];
                ah[fn][3]=tf32_hi(a3); al[fn][3]=a3-ah[fn][3];
            }
            float bh_[8][2], bl_[8][2];
            #pragma unroll
            for (int fm = 0; fm < 8; fm++) {
                int c = f_off + fm*8 + g;
                float b0 = Hs[ks + t    ][c];
                float b1 = Hs[ks + t + 4][c];
                bh_[fm][0]=tf32_hi(b0); bl_[fm][0]=b0-bh_[fm][0];
                bh_[fm][1]=tf32_hi(b1); bl_[fm][1]=b1-bh_[fm][1];
            }
            #pragma unroll
            for (int fn = 0; fn < 2; fn++)
                #pragma unroll
                for (int fm = 0; fm < 8; fm++) {
                    mma_tf32(acc[fn][fm], ah[fn], bh_[fm]);
                    mma_tf32(acc[fn][fm], ah[fn], bl_[fm]);
                    mma_tf32(acc[fn][fm], al[fn], bh_[fm]);
                }
        }
        __syncthreads();
    }

    const float* xold = (h == 0) ? xoldA : xoldB;
    float* xout = (h == 0) ? xoutA : xoutB;
    const float* degp = g_degs + (size_t)hb*CN;
    #pragma unroll
    for (int fn = 0; fn < 2; fn++)
        #pragma unroll
        for (int half = 0; half < 2; half++) {
            int n = n0 + n_off + fn*16 + g + half*8;
            float dinv = 1.0f / degp[n];
            #pragma unroll
            for (int fm = 0; fm < 8; fm++) {
                int f = f0 + f_off + fm*8 + 2*t;
                size_t idx = (size_t)b*CN*CD + (size_t)n*CD + f;
                float v0 = acc[fn][fm][half*2]   * dinv + bias[f];
                float v1 = acc[fn][fm][half*2+1] * dinv + bias[f+1];
                float2 o;
                o.x = xold[idx]     + fmaxf(v0, 0.0f);
                o.y = xold[idx + 1] + fmaxf(v1, 0.0f);
                *(float2*)&xout[idx] = o;
            }
        }
}

// =====================================================================
extern "C" void kernel_launch(void* const* d_in, const int* in_sizes, int n_in,
                              void* d_out, int out_size)
{
    (void)in_sizes; (void)n_in; (void)out_size;
    const float* X   = (const float*)d_in[0];
    const int*   adj = (const int*)d_in[1];
    const float* Wq  = (const float*)d_in[2];
    const float* bq  = (const float*)d_in[3];
    const float* Wk  = (const float*)d_in[4];
    const float* bk  = (const float*)d_in[5];
    const float* gW  = (const float*)d_in[6];
    const float* gb  = (const float*)d_in[7];
    const float* aW  = (const float*)d_in[8];
    const float* ab  = (const float*)d_in[9];

    float* out = (float*)d_out;                      // (B,N,D)
    float* ga  = out + (size_t)CB*CN*CD;             // (H,B,N,N)

    float *qb, *kb, *h1, *x0, *x1, *dg;
    cudaGetSymbolAddress((void**)&qb, g_q);
    cudaGetSymbolAddress((void**)&kb, g_k);
    cudaGetSymbolAddress((void**)&h1, g_h1);
    cudaGetSymbolAddress((void**)&x0, g_x0);
    cudaGetSymbolAddress((void**)&x1, g_x1);
    cudaGetSymbolAddress((void**)&dg, g_degs);

    const dim3 gproj(CB*CN/64, CD/64);               // 128 x 4

    // Q/K projections for each edge type
    for (int e = 0; e < CE; e++) {
        gemm_xw_kernel<<<gproj, 256>>>(X, nullptr, Wq + (size_t)e*CD*CD, bq + e*CD,
                                       qb + (size_t)e*CB*CN*CD, CD);
        gemm_xw_kernel<<<gproj, 256>>>(X, nullptr, Wk + (size_t)e*CD*CD, bk + e*CD,
                                       kb + (size_t)e*CB*CN*CD, CD);
    }

    // Edge-typed scores -> graph_attention region, then softmax (+degs)
    scores_kernel<<<dim3(CN/64, CN/128, CB*CH), 256>>>(adj, ga);
    softmax_kernel<<<dim3(CN, CH*CB), 256>>>(ga, dg);

    // GCN iteration 0: h1 = X @ gcn_W[0] (shared by both heads)
    gemm_xw_kernel<<<gproj, 256>>>(X, nullptr, gW, nullptr, h1, CD);
    spmm_kernel<<<dim3(CD/128, CN/128, CH*CB), 256>>>(ga, X, X, x0, x1, gb, 0);

    // GCN iteration 1, head 0
    gemm_xw_kernel<<<gproj, 256>>>(x0, nullptr, gW + (size_t)CD*CD, nullptr, h1, CD);
    spmm_kernel<<<dim3(CD/128, CN/128, CB), 256>>>(ga, x0, x0, x0, x0, gb + CD, 0);

    // GCN iteration 1, head 1
    gemm_xw_kernel<<<gproj, 256>>>(x1, nullptr, gW + (size_t)CD*CD, nullptr, h1, CD);
    spmm_kernel<<<dim3(CD/128, CN/128, CB), 256>>>(ga, x1, x1, x1, x1, gb + CD, 4);

    // Aggregation: out = concat(x0, x1) @ agg_W + agg_b
    gemm_xw_kernel<<<gproj, 256>>>(x0, x1, aW, ab, out, 2*CD);
}

// round 7
// speedup vs baseline: 1.4596x; 1.2287x over previous
#include <cuda_runtime.h>
#include <cstdint>

#define CB 4
#define CN 2048
#define CD 256
#define CE 3
#define CH 2
#define CDK 128
#define NEGF -1000000000.0f
#define QK_PAD 20
#define MAXJ 8

// ---- scratch (static device globals; no allocation allowed) ----
__device__ float g_q[(size_t)CE*CB*CN*CD];     // per-edge Q projections
__device__ float g_k[(size_t)CE*CB*CN*CD];     // per-edge K projections
__device__ float g_h1a[(size_t)CB*CN*CD];      // GCN h1 buffer (head 0 / shared)
__device__ float g_h1b[(size_t)CB*CN*CD];      // GCN h1 buffer (head 1)
__device__ float g_x0[(size_t)CB*CN*CD];       // head-0 node state
__device__ float g_x1[(size_t)CB*CN*CD];       // head-1 node state
__device__ float g_degs[(size_t)CH*CB*CN];     // row sums of attn (degs)

// ---------------------------------------------------------------------
// tf32 MMA helpers: m16n8k8, row.col, fp32 accumulate.
// Split-precision: x = hi + lo with hi = top-10-mantissa-bits(x);
// x*y ~= hi_x*hi_y + hi_x*lo_y + lo_x*hi_y  (3 MMAs, ~2^-21 rel err)
// ---------------------------------------------------------------------
__device__ __forceinline__ float tf32_hi(float x) {
    return __uint_as_float(__float_as_uint(x) & 0xFFFFE000u);
}

__device__ __forceinline__ void mma_tf32(float* c, const float* a, const float* b) {
    asm volatile(
        "mma.sync.aligned.m16n8k8.row.col.f32.tf32.tf32.f32 "
        "{%0,%1,%2,%3}, {%4,%5,%6,%7}, {%8,%9}, {%0,%1,%2,%3};\n"
        : "+f"(c[0]), "+f"(c[1]), "+f"(c[2]), "+f"(c[3])
        : "r"(__float_as_uint(a[0])), "r"(__float_as_uint(a[1])),
          "r"(__float_as_uint(a[2])), "r"(__float_as_uint(a[3])),
          "r"(__float_as_uint(b[0])), "r"(__float_as_uint(b[1])));
}

// Shared 128x128 tile compute: As is m-major [128][QK_PAD] (16 k values),
// Hs is k-major [16][136] (128 n values). fm-outer so B-split temps stay
// at 4 live registers.
__device__ __forceinline__ void tile_compute_128(
    const float (&As)[128][QK_PAD], const float (&Hs)[16][136],
    float (&acc)[2][8][4], int m_off, int n_off, int g, int t)
{
    #pragma unroll
    for (int ks = 0; ks < 16; ks += 8) {
        float ah[2][4], al[2][4];
        #pragma unroll
        for (int fn = 0; fn < 2; fn++) {
            int r0 = m_off + fn*16 + g;
            float a0 = As[r0    ][ks + t];
            float a1 = As[r0 + 8][ks + t];
            float a2 = As[r0    ][ks + t + 4];
            float a3 = As[r0 + 8][ks + t + 4];
            ah[fn][0]=tf32_hi(a0); al[fn][0]=a0-ah[fn][0];
            ah[fn][1]=tf32_hi(a1); al[fn][1]=a1-ah[fn][1];
            ah[fn][2]=tf32_hi(a2); al[fn][2]=a2-ah[fn][2];
            ah[fn][3]=tf32_hi(a3); al[fn][3]=a3-ah[fn][3];
        }
        #pragma unroll
        for (int fm = 0; fm < 8; fm++) {
            int c = n_off + fm*8 + g;
            float b0 = Hs[ks + t    ][c];
            float b1 = Hs[ks + t + 4][c];
            float bh[2], bl[2];
            bh[0]=tf32_hi(b0); bl[0]=b0-bh[0];
            bh[1]=tf32_hi(b1); bl[1]=b1-bh[1];
            #pragma unroll
            for (int fn = 0; fn < 2; fn++) {
                mma_tf32(acc[fn][fm], ah[fn], bh);
                mma_tf32(acc[fn][fm], ah[fn], bl);
                mma_tf32(acc[fn][fm], al[fn], bh);
            }
        }
    }
}

// =====================================================================
// Batched tf32-split GEMM: per z-job, C[8192,256] = A[8192,K] @ W[K,256]
// (+bias). split=1 reads k<256 from A0, k>=256 from A1 (concat).
// Tile 128(m) x 128(n), k-chunk 16, register-prefetch pipelined.
// =====================================================================
struct GemmJobs {
    const float* A0[MAXJ];
    const float* A1[MAXJ];
    const float* W[MAXJ];
    const float* bias[MAXJ];
    float* C[MAXJ];
    int split[MAXJ];
};

__global__ void __launch_bounds__(256, 2) gemm_mma_kernel(GemmJobs jobs, int K)
{
    __shared__ float As[128][QK_PAD];
    __shared__ float Ws[16][136];
    const int tid = threadIdx.x;
    const int wid = tid >> 5;
    const int lane = tid & 31;
    const int g = lane >> 2;
    const int t = lane & 3;
    const int m_off = (wid & 3) * 32;
    const int n_off = (wid >> 2) * 64;
    const int z = blockIdx.z;
    const float* A0 = jobs.A0[z];
    const float* A1 = jobs.A1[z];
    const float* W  = jobs.W[z];
    const float* bias = jobs.bias[z];
    float* C = jobs.C[z];
    const int split = jobs.split[z];
    const int bn0 = blockIdx.x * 128;
    const int bm0 = blockIdx.y * 128;

    float acc[2][8][4];
    #pragma unroll
    for (int i = 0; i < 2; i++)
        #pragma unroll
        for (int j = 0; j < 8; j++)
            #pragma unroll
            for (int c = 0; c < 4; c++) acc[i][j][c] = 0.0f;

    float4 pa[2], pw[2];
    auto loadA = [&](int kc) {
        #pragma unroll
        for (int it = 0; it < 2; it++) {
            int id = tid + it * 256;
            int r = id >> 2;
            int k4 = id & 3;
            int gk = kc + k4 * 4;
            const float* base = A0; int col = gk;
            if (split && gk >= 256) { base = A1; col = gk - 256; }
            pa[it] = *(const float4*)(base + (size_t)(bm0 + r) * 256 + col);
        }
    };
    auto loadW = [&](int kc) {
        #pragma unroll
        for (int it = 0; it < 2; it++) {
            int id = tid + it * 256;
            int f4 = id & 31;
            int k = id >> 5;
            pw[it] = *(const float4*)(W + (size_t)(kc + k) * 256 + bn0 + f4 * 4);
        }
    };

    loadA(0); loadW(0);
    for (int kc = 0; kc < K; kc += 16) {
        #pragma unroll
        for (int it = 0; it < 2; it++) {
            int id = tid + it * 256;
            int r = id >> 2, k4 = id & 3;
            *(float4*)&As[r][k4*4] = pa[it];
        }
        #pragma unroll
        for (int it = 0; it < 2; it++) {
            int id = tid + it * 256;
            int f4 = id & 31, k = id >> 5;
            *(float4*)&Ws[k][f4*4] = pw[it];
        }
        __syncthreads();
        if (kc + 16 < K) { loadA(kc + 16); loadW(kc + 16); }
        tile_compute_128(As, Ws, acc, m_off, n_off, g, t);
        __syncthreads();
    }

    #pragma unroll
    for (int fn = 0; fn < 2; fn++)
        #pragma unroll
        for (int half = 0; half < 2; half++) {
            int m = bm0 + m_off + fn*16 + g + half*8;
            #pragma unroll
            for (int fm = 0; fm < 8; fm++) {
                int n = bn0 + n_off + fm*8 + 2*t;
                float bv0 = bias ? bias[n]     : 0.0f;
                float bv1 = bias ? bias[n + 1] : 0.0f;
                float2 o;
                o.x = acc[fn][fm][half*2]   + bv0;
                o.y = acc[fn][fm][half*2+1] + bv1;
                *(float2*)&C[(size_t)m*256 + n] = o;
            }
        }
}

// =====================================================================
// Edge-typed attention scores (tensor-core tf32-split, pipelined).
// Block tile: 128(n) x 64(m) for one (b,h); 8 warps of 32x32.
// =====================================================================
__global__ void __launch_bounds__(256) scores_kernel(
    const int* __restrict__ adj, float* __restrict__ ga)
{
    __shared__ float Qs[CE][128][QK_PAD];
    __shared__ float Ks[CE][64][QK_PAD];
    const int tid = threadIdx.x;
    const int wid = tid >> 5;
    const int lane = tid & 31;
    const int g = lane >> 2;
    const int t = lane & 3;
    const int n_off = (wid & 3) * 32;
    const int m_off = (wid >> 2) * 32;
    const int bh = blockIdx.z;
    const int b = bh >> 1;
    const int h = bh & 1;
    const int m0 = blockIdx.x * 64;
    const int n0 = blockIdx.y * 128;

    float acc[CE][2][4][4];
    #pragma unroll
    for (int e = 0; e < CE; e++)
        #pragma unroll
        for (int i = 0; i < 2; i++)
            #pragma unroll
            for (int j = 0; j < 4; j++)
                #pragma unroll
                for (int c = 0; c < 4; c++) acc[e][i][j][c] = 0.0f;

    float4 pq[6], pk[3];
    auto loadQ = [&](int kc) {
        #pragma unroll
        for (int it = 0; it < 6; it++) {
            int id = tid + it * 256;
            int k4 = id & 3;
            int n  = (id >> 2) & 127;
            int e  = id >> 9;
            pq[it] = *(const float4*)(g_q + ((size_t)(e*CB + b)*CN + n0 + n)*CD
                                          + h*CDK + kc + k4*4);
        }
    };
    auto loadK = [&](int kc) {
        #pragma unroll
        for (int it = 0; it < 3; it++) {
            int id = tid + it * 256;
            int k4 = id & 3;
            int m  = (id >> 2) & 63;
            int e  = id >> 8;
            pk[it] = *(const float4*)(g_k + ((size_t)(e*CB + b)*CN + m0 + m)*CD
                                          + h*CDK + kc + k4*4);
        }
    };

    loadQ(0); loadK(0);
    for (int kc = 0; kc < CDK; kc += 16) {
        #pragma unroll
        for (int it = 0; it < 6; it++) {
            int id = tid + it * 256;
            int k4 = id & 3;
            int n  = (id >> 2) & 127;
            int e  = id >> 9;
            *(float4*)&Qs[e][n][k4*4] = pq[it];
        }
        #pragma unroll
        for (int it = 0; it < 3; it++) {
            int id = tid + it * 256;
            int k4 = id & 3;
            int m  = (id >> 2) & 63;
            int e  = id >> 8;
            *(float4*)&Ks[e][m][k4*4] = pk[it];
        }
        __syncthreads();
        if (kc + 16 < CDK) { loadQ(kc + 16); loadK(kc + 16); }
        #pragma unroll
        for (int ks = 0; ks < 16; ks += 8) {
            #pragma unroll
            for (int e = 0; e < CE; e++) {
                float ah[2][4], al[2][4];
                #pragma unroll
                for (int fn = 0; fn < 2; fn++) {
                    int r0 = n_off + fn*16 + g;
                    float a0 = Qs[e][r0    ][ks + t];
                    float a1 = Qs[e][r0 + 8][ks + t];
                    float a2 = Qs[e][r0    ][ks + t + 4];
                    float a3 = Qs[e][r0 + 8][ks + t + 4];
                    ah[fn][0]=tf32_hi(a0); al[fn][0]=a0-ah[fn][0];
                    ah[fn][1]=tf32_hi(a1); al[fn][1]=a1-ah[fn][1];
                    ah[fn][2]=tf32_hi(a2); al[fn][2]=a2-ah[fn][2];
                    ah[fn][3]=tf32_hi(a3); al[fn][3]=a3-ah[fn][3];
                }
                #pragma unroll
                for (int fm = 0; fm < 4; fm++) {
                    int r = m_off + fm*8 + g;
                    float b0 = Ks[e][r][ks + t];
                    float b1 = Ks[e][r][ks + t + 4];
                    float bh_[2], bl_[2];
                    bh_[0]=tf32_hi(b0); bl_[0]=b0-bh_[0];
                    bh_[1]=tf32_hi(b1); bl_[1]=b1-bh_[1];
                    #pragma unroll
                    for (int fn = 0; fn < 2; fn++) {
                        mma_tf32(acc[e][fn][fm], ah[fn], bh_);
                        mma_tf32(acc[e][fn][fm], ah[fn], bl_);
                        mma_tf32(acc[e][fn][fm], al[fn], bh_);
                    }
                }
            }
        }
        __syncthreads();
    }

    const float scale = 0.088388347648318447f;  // 1/sqrt(128)
    float* gout = ga + (size_t)(h*CB + b)*CN*CN;
    const int* adjb = adj + (size_t)b*CN*CN;
    #pragma unroll
    for (int fn = 0; fn < 2; fn++)
        #pragma unroll
        for (int fm = 0; fm < 4; fm++)
            #pragma unroll
            for (int half = 0; half < 2; half++) {
                int n = n0 + n_off + fn*16 + g + half*8;
                int m = m0 + m_off + fm*8 + 2*t;
                int2 av = *(const int2*)&adjb[(size_t)n*CN + m];
                float2 o;
                {
                    float r = 0.0f;
                    if (av.x == 1)      r = acc[0][fn][fm][half*2]*scale;
                    else if (av.x == 2) r = acc[1][fn][fm][half*2]*scale;
                    else if (av.x == 3) r = acc[2][fn][fm][half*2]*scale;
                    o.x = (r == 0.0f) ? NEGF : r;
                }
                {
                    float r = 0.0f;
                    if (av.y == 1)      r = acc[0][fn][fm][half*2+1]*scale;
                    else if (av.y == 2) r = acc[1][fn][fm][half*2+1]*scale;
                    else if (av.y == 3) r = acc[2][fn][fm][half*2+1]*scale;
                    o.y = (r == 0.0f) ? NEGF : r;
                }
                *(float2*)&gout[(size_t)n*CN + m] = o;
            }
}

// =====================================================================
// Row softmax over 2048 + degs.
// =====================================================================
__global__ void __launch_bounds__(256) softmax_kernel(
    float* __restrict__ ga, float* __restrict__ degs)
{
    float* p = ga + ((size_t)blockIdx.y * CN + blockIdx.x) * CN;
    const int tid = threadIdx.x;
    float v[8];
    #pragma unroll
    for (int i = 0; i < 8; i++) v[i] = p[tid + 256*i];
    float lmax = v[0];
    #pragma unroll
    for (int i = 1; i < 8; i++) lmax = fmaxf(lmax, v[i]);
    #pragma unroll
    for (int o = 16; o; o >>= 1) lmax = fmaxf(lmax, __shfl_xor_sync(0xffffffffu, lmax, o));
    __shared__ float red[8];
    if ((tid & 31) == 0) red[tid >> 5] = lmax;
    __syncthreads();
    float rmax = red[0];
    #pragma unroll
    for (int i = 1; i < 8; i++) rmax = fmaxf(rmax, red[i]);
    float lsum = 0.0f;
    #pragma unroll
    for (int i = 0; i < 8; i++) { v[i] = __expf(v[i] - rmax); lsum += v[i]; }
    #pragma unroll
    for (int o = 16; o; o >>= 1) lsum += __shfl_xor_sync(0xffffffffu, lsum, o);
    __syncthreads();
    __shared__ float red2[8];
    if ((tid & 31) == 0) red2[tid >> 5] = lsum;
    __syncthreads();
    float rsum = 0.0f;
    #pragma unroll
    for (int i = 0; i < 8; i++) rsum += red2[i];
    float rinv = 1.0f / rsum;
    float lw = 0.0f;
    #pragma unroll
    for (int i = 0; i < 8; i++) { float w = v[i]*rinv; p[tid + 256*i] = w; lw += w; }
    #pragma unroll
    for (int o = 16; o; o >>= 1) lw += __shfl_xor_sync(0xffffffffu, lw, o);
    __shared__ float red3[8];
    if ((tid & 31) == 0) red3[tid >> 5] = lw;
    __syncthreads();
    if (tid == 0) {
        float s = 0.0f;
        #pragma unroll
        for (int i = 0; i < 8; i++) s += red3[i];
        degs[(size_t)blockIdx.y*CN + blockIdx.x] = s;
    }
}

// =====================================================================
// GCN aggregation (tensor-core tf32-split, pipelined): C = attn(hb) @ h1,
// epilogue x_out = x_old + relu(C/deg + gcn_b).
// h1 source selected per head (h==0 -> h1A, h==1 -> h1B).
// =====================================================================
__global__ void __launch_bounds__(256, 2) spmm_kernel(
    const float* __restrict__ ga,
    const float* __restrict__ h1A, const float* __restrict__ h1B,
    const float* __restrict__ xoldA, const float* __restrict__ xoldB,
    float* __restrict__ xoutA, float* __restrict__ xoutB,
    const float* __restrict__ bias, int hb0)
{
    __shared__ float As[128][QK_PAD];
    __shared__ float Hs[16][136];
    const int tid = threadIdx.x;
    const int wid = tid >> 5;
    const int lane = tid & 31;
    const int g = lane >> 2;
    const int t = lane & 3;
    const int n_off = (wid & 3) * 32;
    const int f_off = (wid >> 2) * 64;
    const int hb = hb0 + blockIdx.z;
    const int h = hb / CB;
    const int b = hb % CB;
    const int f0 = blockIdx.x * 128;
    const int n0 = blockIdx.y * 128;
    const float* Ab = ga + (size_t)hb*CN*CN;
    const float* Hb = ((h == 0) ? h1A : h1B) + (size_t)b*CN*CD;

    float acc[2][8][4];
    #pragma unroll
    for (int i = 0; i < 2; i++)
        #pragma unroll
        for (int j = 0; j < 8; j++)
            #pragma unroll
            for (int c = 0; c < 4; c++) acc[i][j][c] = 0.0f;

    float4 pa[2], ph[2];
    auto loadA = [&](int kc) {
        #pragma unroll
        for (int it = 0; it < 2; it++) {
            int id = tid + it * 256;
            int r = id >> 2, k4 = id & 3;
            pa[it] = *(const float4*)(Ab + (size_t)(n0 + r)*CN + kc + k4*4);
        }
    };
    auto loadH = [&](int kc) {
        #pragma unroll
        for (int it = 0; it < 2; it++) {
            int id = tid + it * 256;
            int f4 = id & 31, k = id >> 5;
            ph[it] = *(const float4*)(Hb + (size_t)(kc + k)*CD + f0 + f4*4);
        }
    };

    loadA(0); loadH(0);
    for (int kc = 0; kc < CN; kc += 16) {
        #pragma unroll
        for (int it = 0; it < 2; it++) {
            int id = tid + it * 256;
            int r = id >> 2, k4 = id & 3;
            *(float4*)&As[r][k4*4] = pa[it];
        }
        #pragma unroll
        for (int it = 0; it < 2; it++) {
            int id = tid + it * 256;
            int f4 = id & 31, k = id >> 5;
            *(float4*)&Hs[k][f4*4] = ph[it];
        }
        __syncthreads();
        if (kc + 16 < CN) { loadA(kc + 16); loadH(kc + 16); }
        tile_compute_128(As, Hs, acc, n_off, f_off, g, t);
        __syncthreads();
    }

    const float* xold = (h == 0) ? xoldA : xoldB;
    float* xout = (h == 0) ? xoutA : xoutB;
    const float* degp = g_degs + (size_t)hb*CN;
    #pragma unroll
    for (int fn = 0; fn < 2; fn++)
        #pragma unroll
        for (int half = 0; half < 2; half++) {
            int n = n0 + n_off + fn*16 + g + half*8;
            float dinv = 1.0f / degp[n];
            #pragma unroll
            for (int fm = 0; fm < 8; fm++) {
                int f = f0 + f_off + fm*8 + 2*t;
                size_t idx = (size_t)b*CN*CD + (size_t)n*CD + f;
                float v0 = acc[fn][fm][half*2]   * dinv + bias[f];
                float v1 = acc[fn][fm][half*2+1] * dinv + bias[f+1];
                float2 o;
                o.x = xold[idx]     + fmaxf(v0, 0.0f);
                o.y = xold[idx + 1] + fmaxf(v1, 0.0f);
                *(float2*)&xout[idx] = o;
            }
        }
}

// =====================================================================
extern "C" void kernel_launch(void* const* d_in, const int* in_sizes, int n_in,
                              void* d_out, int out_size)
{
    (void)in_sizes; (void)n_in; (void)out_size;
    const float* X   = (const float*)d_in[0];
    const int*   adj = (const int*)d_in[1];
    const float* Wq  = (const float*)d_in[2];
    const float* bq  = (const float*)d_in[3];
    const float* Wk  = (const float*)d_in[4];
    const float* bk  = (const float*)d_in[5];
    const float* gW  = (const float*)d_in[6];
    const float* gb  = (const float*)d_in[7];
    const float* aW  = (const float*)d_in[8];
    const float* ab  = (const float*)d_in[9];

    float* out = (float*)d_out;                      // (B,N,D)
    float* ga  = out + (size_t)CB*CN*CD;             // (H,B,N,N)

    float *qb, *kb, *h1a, *h1b, *x0, *x1, *dg;
    cudaGetSymbolAddress((void**)&qb,  g_q);
    cudaGetSymbolAddress((void**)&kb,  g_k);
    cudaGetSymbolAddress((void**)&h1a, g_h1a);
    cudaGetSymbolAddress((void**)&h1b, g_h1b);
    cudaGetSymbolAddress((void**)&x0,  g_x0);
    cudaGetSymbolAddress((void**)&x1,  g_x1);
    cudaGetSymbolAddress((void**)&dg,  g_degs);

    // Launch 1: 6 projections + iter-0 h1, all A = X, one batched launch (z=7)
    GemmJobs J1 = {};
    for (int e = 0; e < CE; e++) {
        J1.A0[2*e] = X;  J1.A1[2*e] = X;
        J1.W[2*e] = Wq + (size_t)e*CD*CD;  J1.bias[2*e] = bq + e*CD;
        J1.C[2*e] = qb + (size_t)e*CB*CN*CD;  J1.split[2*e] = 0;
        J1.A0[2*e+1] = X;  J1.A1[2*e+1] = X;
        J1.W[2*e+1] = Wk + (size_t)e*CD*CD;  J1.bias[2*e+1] = bk + e*CD;
        J1.C[2*e+1] = kb + (size_t)e*CB*CN*CD;  J1.split[2*e+1] = 0;
    }
    J1.A0[6] = X;  J1.A1[6] = X;  J1.W[6] = gW;  J1.bias[6] = nullptr;
    J1.C[6] = h1a;  J1.split[6] = 0;
    gemm_mma_kernel<<<dim3(2, 64, 7), 256>>>(J1, CD);

    // Scores -> graph_attention region, then softmax (+degs)
    scores_kernel<<<dim3(CN/64, CN/128, CB*CH), 256>>>(adj, ga);
    softmax_kernel<<<dim3(CN, CH*CB), 256>>>(ga, dg);

    // GCN iteration 0: both heads share h1a; one z=8 launch
    spmm_kernel<<<dim3(CD/128, CN/128, CH*CB), 256>>>(ga, h1a, h1a, X, X, x0, x1, gb, 0);

    // GCN iteration 1: both h1 gemms in one z=2 launch, then one z=8 spmm
    GemmJobs J2 = {};
    J2.A0[0] = x0;  J2.A1[0] = x0;  J2.W[0] = gW + (size_t)CD*CD;
    J2.bias[0] = nullptr;  J2.C[0] = h1a;  J2.split[0] = 0;
    J2.A0[1] = x1;  J2.A1[1] = x1;  J2.W[1] = gW + (size_t)CD*CD;
    J2.bias[1] = nullptr;  J2.C[1] = h1b;  J2.split[1] = 0;
    gemm_mma_kernel<<<dim3(2, 64, 2), 256>>>(J2, CD);
    spmm_kernel<<<dim3(CD/128, CN/128, CH*CB), 256>>>(ga, h1a, h1b, x0, x1, x0, x1, gb + CD, 0);

    // Aggregation: out = concat(x0, x1) @ agg_W + agg_b (split-K)
    GemmJobs J3 = {};
    J3.A0[0] = x0;  J3.A1[0] = x1;  J3.W[0] = aW;  J3.bias[0] = ab;
    J3.C[0] = out;  J3.split[0] = 1;
    gemm_mma_kernel<<<dim3(2, 64, 1), 256>>>(J3, 2*CD);
}

// round 11
// speedup vs baseline: 1.8029x; 1.2352x over previous
#include <cuda_runtime.h>
#include <cstdint>

#define CB 4
#define CN 2048
#define CD 256
#define CE 3
#define CH 2
#define CDK 128
#define NEGF -1000000000.0f
#define QK_PAD 20
#define MAXJ 8

// ---- scratch (static device globals; no allocation allowed) ----
__device__ float g_q[(size_t)CE*CB*CN*CD];     // per-edge Q projections
__device__ float g_k[(size_t)CE*CB*CN*CD];     // per-edge K projections
__device__ float g_h1a[(size_t)CB*CN*CD];      // GCN h1 buffer (head 0 / shared)
__device__ float g_h1b[(size_t)CB*CN*CD];      // GCN h1 buffer (head 1)
__device__ float g_x0[(size_t)CB*CN*CD];       // head-0 node state
__device__ float g_x1[(size_t)CB*CN*CD];       // head-1 node state
__device__ float g_degs[(size_t)CH*CB*CN];     // row sums of attn (degs)

// ---------------------------------------------------------------------
// tf32 MMA helpers: m16n8k8, row.col, fp32 accumulate. Split-precision
// (hi/lo) -> 3 MMAs per logical MMA, ~2^-21 rel err.
// ---------------------------------------------------------------------
__device__ __forceinline__ float tf32_hi(float x) {
    return __uint_as_float(__float_as_uint(x) & 0xFFFFE000u);
}

__device__ __forceinline__ void mma_tf32(float* c, const float* a, const float* b) {
    asm volatile(
        "mma.sync.aligned.m16n8k8.row.col.f32.tf32.tf32.f32 "
        "{%0,%1,%2,%3}, {%4,%5,%6,%7}, {%8,%9}, {%0,%1,%2,%3};\n"
        : "+f"(c[0]), "+f"(c[1]), "+f"(c[2]), "+f"(c[3])
        : "r"(__float_as_uint(a[0])), "r"(__float_as_uint(a[1])),
          "r"(__float_as_uint(a[2])), "r"(__float_as_uint(a[3])),
          "r"(__float_as_uint(b[0])), "r"(__float_as_uint(b[1])));
}

// Shared 128x128 tile compute: As m-major [128][QK_PAD] (16 k), Hs k-major
// [16][136] (128 n). fm-outer keeps B-split temps at 4 live regs.
__device__ __forceinline__ void tile_compute_128(
    const float (&As)[128][QK_PAD], const float (&Hs)[16][136],
    float (&acc)[2][8][4], int m_off, int n_off, int g, int t)
{
    #pragma unroll
    for (int ks = 0; ks < 16; ks += 8) {
        float ah[2][4], al[2][4];
        #pragma unroll
        for (int fn = 0; fn < 2; fn++) {
            int r0 = m_off + fn*16 + g;
            float a0 = As[r0    ][ks + t];
            float a1 = As[r0 + 8][ks + t];
            float a2 = As[r0    ][ks + t + 4];
            float a3 = As[r0 + 8][ks + t + 4];
            ah[fn][0]=tf32_hi(a0); al[fn][0]=a0-ah[fn][0];
            ah[fn][1]=tf32_hi(a1); al[fn][1]=a1-ah[fn][1];
            ah[fn][2]=tf32_hi(a2); al[fn][2]=a2-ah[fn][2];
            ah[fn][3]=tf32_hi(a3); al[fn][3]=a3-ah[fn][3];
        }
        #pragma unroll
        for (int fm = 0; fm < 8; fm++) {
            int c = n_off + fm*8 + g;
            float b0 = Hs[ks + t    ][c];
            float b1 = Hs[ks + t + 4][c];
            float bh[2], bl[2];
            bh[0]=tf32_hi(b0); bl[0]=b0-bh[0];
            bh[1]=tf32_hi(b1); bl[1]=b1-bh[1];
            #pragma unroll
            for (int fn = 0; fn < 2; fn++) {
                mma_tf32(acc[fn][fm], ah[fn], bh);
                mma_tf32(acc[fn][fm], ah[fn], bl);
                mma_tf32(acc[fn][fm], al[fn], bh);
            }
        }
    }
}

// =====================================================================
// Batched tf32-split GEMM, double-buffered. Per z-job:
// C[8192,256] = A[8192,K] @ W[K,256] (+bias); split=1 -> concat A0|A1.
// =====================================================================
struct GemmJobs {
    const float* A0[MAXJ];
    const float* A1[MAXJ];
    const float* W[MAXJ];
    const float* bias[MAXJ];
    float* C[MAXJ];
    int split[MAXJ];
};

__global__ void __launch_bounds__(256, 2) gemm_mma_kernel(GemmJobs jobs, int K)
{
    __shared__ float As[2][128][QK_PAD];
    __shared__ float Ws[2][16][136];
    const int tid = threadIdx.x;
    const int wid = tid >> 5;
    const int lane = tid & 31;
    const int g = lane >> 2;
    const int t = lane & 3;
    const int m_off = (wid & 3) * 32;
    const int n_off = (wid >> 2) * 64;
    const int z = blockIdx.z;
    const float* A0 = jobs.A0[z];
    const float* A1 = jobs.A1[z];
    const float* W  = jobs.W[z];
    const float* bias = jobs.bias[z];
    float* C = jobs.C[z];
    const int split = jobs.split[z];
    const int bn0 = blockIdx.x * 128;
    const int bm0 = blockIdx.y * 128;

    float acc[2][8][4];
    #pragma unroll
    for (int i = 0; i < 2; i++)
        #pragma unroll
        for (int j = 0; j < 8; j++)
            #pragma unroll
            for (int c = 0; c < 4; c++) acc[i][j][c] = 0.0f;

    float4 pa[2], pw[2];
    auto loadA = [&](int kc) {
        #pragma unroll
        for (int it = 0; it < 2; it++) {
            int id = tid + it * 256;
            int r = id >> 2;
            int k4 = id & 3;
            int gk = kc + k4 * 4;
            const float* base = A0; int col = gk;
            if (split && gk >= 256) { base = A1; col = gk - 256; }
            pa[it] = *(const float4*)(base + (size_t)(bm0 + r) * 256 + col);
        }
    };
    auto loadW = [&](int kc) {
        #pragma unroll
        for (int it = 0; it < 2; it++) {
            int id = tid + it * 256;
            int f4 = id & 31;
            int k = id >> 5;
            pw[it] = *(const float4*)(W + (size_t)(kc + k) * 256 + bn0 + f4 * 4);
        }
    };
    auto stsA = [&](int buf) {
        #pragma unroll
        for (int it = 0; it < 2; it++) {
            int id = tid + it * 256;
            int r = id >> 2, k4 = id & 3;
            *(float4*)&As[buf][r][k4*4] = pa[it];
        }
    };
    auto stsW = [&](int buf) {
        #pragma unroll
        for (int it = 0; it < 2; it++) {
            int id = tid + it * 256;
            int f4 = id & 31, k = id >> 5;
            *(float4*)&Ws[buf][k][f4*4] = pw[it];
        }
    };

    loadA(0); loadW(0);
    stsA(0); stsW(0);
    __syncthreads();
    int cur = 0;
    for (int kc = 0; kc < K; kc += 16) {
        const bool has = (kc + 16 < K);
        if (has) { loadA(kc + 16); loadW(kc + 16); }
        tile_compute_128(As[cur], Ws[cur], acc, m_off, n_off, g, t);
        if (has) { stsA(cur ^ 1); stsW(cur ^ 1); }
        __syncthreads();
        cur ^= 1;
    }

    #pragma unroll
    for (int fn = 0; fn < 2; fn++)
        #pragma unroll
        for (int half = 0; half < 2; half++) {
            int m = bm0 + m_off + fn*16 + g + half*8;
            #pragma unroll
            for (int fm = 0; fm < 8; fm++) {
                int n = bn0 + n_off + fm*8 + 2*t;
                float bv0 = bias ? bias[n]     : 0.0f;
                float bv1 = bias ? bias[n + 1] : 0.0f;
                float2 o;
                o.x = acc[fn][fm][half*2]   + bv0;
                o.y = acc[fn][fm][half*2+1] + bv1;
                *(float2*)&C[(size_t)m*256 + n] = o;
            }
        }
}

// =====================================================================
// Edge-typed attention scores: 3 sequential per-edge passes with a
// running selection tile (merged). smem 30KB double-buffered -> occ 2.
// Block tile 128(n) x 64(m); 8 warps of 32x32.
// =====================================================================
__global__ void __launch_bounds__(256, 2) scores_kernel(
    const int* __restrict__ adj, float* __restrict__ ga)
{
    __shared__ float Qs[2][128][QK_PAD];
    __shared__ float Ks[2][64][QK_PAD];
    const int tid = threadIdx.x;
    const int wid = tid >> 5;
    const int lane = tid & 31;
    const int g = lane >> 2;
    const int t = lane & 3;
    const int n_off = (wid & 3) * 32;
    const int m_off = (wid >> 2) * 32;
    const int bh = blockIdx.z;
    const int b = bh >> 1;
    const int h = bh & 1;
    const int m0 = blockIdx.x * 64;
    const int n0 = blockIdx.y * 128;
    const int* adjb = adj + (size_t)b*CN*CN;
    const float scale = 0.088388347648318447f;  // 1/sqrt(128)

    float merged[2][4][4];
    #pragma unroll
    for (int i = 0; i < 2; i++)
        #pragma unroll
        for (int j = 0; j < 4; j++)
            #pragma unroll
            for (int c = 0; c < 4; c++) merged[i][j][c] = 0.0f;

    for (int e = 0; e < CE; e++) {
        const float* Qb = g_q + ((size_t)(e*CB + b)*CN + n0)*CD + h*CDK;
        const float* Kb = g_k + ((size_t)(e*CB + b)*CN + m0)*CD + h*CDK;

        float acc[2][4][4];
        #pragma unroll
        for (int i = 0; i < 2; i++)
            #pragma unroll
            for (int j = 0; j < 4; j++)
                #pragma unroll
                for (int c = 0; c < 4; c++) acc[i][j][c] = 0.0f;

        float4 pq[2], pk;
        auto loadQ = [&](int kc) {
            #pragma unroll
            for (int it = 0; it < 2; it++) {
                int id = tid + it * 256;
                int k4 = id & 3;
                int n  = id >> 2;
                pq[it] = *(const float4*)(Qb + (size_t)n*CD + kc + k4*4);
            }
        };
        auto loadK = [&](int kc) {
            int k4 = tid & 3;
            int m  = tid >> 2;
            pk = *(const float4*)(Kb + (size_t)m*CD + kc + k4*4);
        };
        auto stsQ = [&](int buf) {
            #pragma unroll
            for (int it = 0; it < 2; it++) {
                int id = tid + it * 256;
                int k4 = id & 3, n = id >> 2;
                *(float4*)&Qs[buf][n][k4*4] = pq[it];
            }
        };
        auto stsK = [&](int buf) {
            int k4 = tid & 3, m = tid >> 2;
            *(float4*)&Ks[buf][m][k4*4] = pk;
        };

        loadQ(0); loadK(0);
        stsQ(0); stsK(0);
        __syncthreads();
        int cur = 0;
        for (int kc = 0; kc < CDK; kc += 16) {
            const bool has = (kc + 16 < CDK);
            if (has) { loadQ(kc + 16); loadK(kc + 16); }
            #pragma unroll
            for (int ks = 0; ks < 16; ks += 8) {
                float ah[2][4], al[2][4];
                #pragma unroll
                for (int fn = 0; fn < 2; fn++) {
                    int r0 = n_off + fn*16 + g;
                    float a0 = Qs[cur][r0    ][ks + t];
                    float a1 = Qs[cur][r0 + 8][ks + t];
                    float a2 = Qs[cur][r0    ][ks + t + 4];
                    float a3 = Qs[cur][r0 + 8][ks + t + 4];
                    ah[fn][0]=tf32_hi(a0); al[fn][0]=a0-ah[fn][0];
                    ah[fn][1]=tf32_hi(a1); al[fn][1]=a1-ah[fn][1];
                    ah[fn][2]=tf32_hi(a2); al[fn][2]=a2-ah[fn][2];
                    ah[fn][3]=tf32_hi(a3); al[fn][3]=a3-ah[fn][3];
                }
                #pragma unroll
                for (int fm = 0; fm < 4; fm++) {
                    int r = m_off + fm*8 + g;
                    float b0 = Ks[cur][r][ks + t];
                    float b1 = Ks[cur][r][ks + t + 4];
                    float bh_[2], bl_[2];
                    bh_[0]=tf32_hi(b0); bl_[0]=b0-bh_[0];
                    bh_[1]=tf32_hi(b1); bl_[1]=b1-bh_[1];
                    #pragma unroll
                    for (int fn = 0; fn < 2; fn++) {
                        mma_tf32(acc[fn][fm], ah[fn], bh_);
                        mma_tf32(acc[fn][fm], ah[fn], bl_);
                        mma_tf32(acc[fn][fm], al[fn], bh_);
                    }
                }
            }
            if (has) { stsQ(cur ^ 1); stsK(cur ^ 1); }
            __syncthreads();
            cur ^= 1;
        }

        // merge this edge's scores where adj == e+1 (adj tile L1/L2 resident)
        #pragma unroll
        for (int fn = 0; fn < 2; fn++)
            #pragma unroll
            for (int fm = 0; fm < 4; fm++)
                #pragma unroll
                for (int half = 0; half < 2; half++) {
                    int n = n0 + n_off + fn*16 + g + half*8;
                    int m = m0 + m_off + fm*8 + 2*t;
                    int2 av = *(const int2*)&adjb[(size_t)n*CN + m];
                    if (av.x == e + 1) merged[fn][fm][half*2]   = acc[fn][fm][half*2]   * scale;
                    if (av.y == e + 1) merged[fn][fm][half*2+1] = acc[fn][fm][half*2+1] * scale;
                }
    }

    float* gout = ga + (size_t)(h*CB + b)*CN*CN;
    #pragma unroll
    for (int fn = 0; fn < 2; fn++)
        #pragma unroll
        for (int fm = 0; fm < 4; fm++)
            #pragma unroll
            for (int half = 0; half < 2; half++) {
                int n = n0 + n_off + fn*16 + g + half*8;
                int m = m0 + m_off + fm*8 + 2*t;
                float r0 = merged[fn][fm][half*2];
                float r1 = merged[fn][fm][half*2+1];
                float2 o;
                o.x = (r0 == 0.0f) ? NEGF : r0;
                o.y = (r1 == 0.0f) ? NEGF : r1;
                *(float2*)&gout[(size_t)n*CN + m] = o;
            }
}

// =====================================================================
// Row softmax over 2048 + degs.
// =====================================================================
__global__ void __launch_bounds__(256) softmax_kernel(
    float* __restrict__ ga, float* __restrict__ degs)
{
    float* p = ga + ((size_t)blockIdx.y * CN + blockIdx.x) * CN;
    const int tid = threadIdx.x;
    float v[8];
    #pragma unroll
    for (int i = 0; i < 8; i++) v[i] = p[tid + 256*i];
    float lmax = v[0];
    #pragma unroll
    for (int i = 1; i < 8; i++) lmax = fmaxf(lmax, v[i]);
    #pragma unroll
    for (int o = 16; o; o >>= 1) lmax = fmaxf(lmax, __shfl_xor_sync(0xffffffffu, lmax, o));
    __shared__ float red[8];
    if ((tid & 31) == 0) red[tid >> 5] = lmax;
    __syncthreads();
    float rmax = red[0];
    #pragma unroll
    for (int i = 1; i < 8; i++) rmax = fmaxf(rmax, red[i]);
    float lsum = 0.0f;
    #pragma unroll
    for (int i = 0; i < 8; i++) { v[i] = __expf(v[i] - rmax); lsum += v[i]; }
    #pragma unroll
    for (int o = 16; o; o >>= 1) lsum += __shfl_xor_sync(0xffffffffu, lsum, o);
    __syncthreads();
    __shared__ float red2[8];
    if ((tid & 31) == 0) red2[tid >> 5] = lsum;
    __syncthreads();
    float rsum = 0.0f;
    #pragma unroll
    for (int i = 0; i < 8; i++) rsum += red2[i];
    float rinv = 1.0f / rsum;
    float lw = 0.0f;
    #pragma unroll
    for (int i = 0; i < 8; i++) { float w = v[i]*rinv; p[tid + 256*i] = w; lw += w; }
    #pragma unroll
    for (int o = 16; o; o >>= 1) lw += __shfl_xor_sync(0xffffffffu, lw, o);
    __shared__ float red3[8];
    if ((tid & 31) == 0) red3[tid >> 5] = lw;
    __syncthreads();
    if (tid == 0) {
        float s = 0.0f;
        #pragma unroll
        for (int i = 0; i < 8; i++) s += red3[i];
        degs[(size_t)blockIdx.y*CN + blockIdx.x] = s;
    }
}

// =====================================================================
// GCN aggregation (tf32-split, double-buffered): C = attn(hb) @ h1,
// epilogue x_out = x_old + relu(C/deg + gcn_b).
// =====================================================================
__global__ void __launch_bounds__(256, 2) spmm_kernel(
    const float* __restrict__ ga,
    const float* __restrict__ h1A, const float* __restrict__ h1B,
    const float* __restrict__ xoldA, const float* __restrict__ xoldB,
    float* __restrict__ xoutA, float* __restrict__ xoutB,
    const float* __restrict__ bias, int hb0)
{
    __shared__ float As[2][128][QK_PAD];
    __shared__ float Hs[2][16][136];
    const int tid = threadIdx.x;
    const int wid = tid >> 5;
    const int lane = tid & 31;
    const int g = lane >> 2;
    const int t = lane & 3;
    const int n_off = (wid & 3) * 32;
    const int f_off = (wid >> 2) * 64;
    const int hb = hb0 + blockIdx.z;
    const int h = hb / CB;
    const int b = hb % CB;
    const int f0 = blockIdx.x * 128;
    const int n0 = blockIdx.y * 128;
    const float* Ab = ga + (size_t)hb*CN*CN;
    const float* Hb = ((h == 0) ? h1A : h1B) + (size_t)b*CN*CD;

    float acc[2][8][4];
    #pragma unroll
    for (int i = 0; i < 2; i++)
        #pragma unroll
        for (int j = 0; j < 8; j++)
            #pragma unroll
            for (int c = 0; c < 4; c++) acc[i][j][c] = 0.0f;

    float4 pa[2], ph[2];
    auto loadA = [&](int kc) {
        #pragma unroll
        for (int it = 0; it < 2; it++) {
            int id = tid + it * 256;
            int r = id >> 2, k4 = id & 3;
            pa[it] = *(const float4*)(Ab + (size_t)(n0 + r)*CN + kc + k4*4);
        }
    };
    auto loadH = [&](int kc) {
        #pragma unroll
        for (int it = 0; it < 2; it++) {
            int id = tid + it * 256;
            int f4 = id & 31, k = id >> 5;
            ph[it] = *(const float4*)(Hb + (size_t)(kc + k)*CD + f0 + f4*4);
        }
    };
    auto stsA = [&](int buf) {
        #pragma unroll
        for (int it = 0; it < 2; it++) {
            int id = tid + it * 256;
            int r = id >> 2, k4 = id & 3;
            *(float4*)&As[buf][r][k4*4] = pa[it];
        }
    };
    auto stsH = [&](int buf) {
        #pragma unroll
        for (int it = 0; it < 2; it++) {
            int id = tid + it * 256;
            int f4 = id & 31, k = id >> 5;
            *(float4*)&Hs[buf][k][f4*4] = ph[it];
        }
    };

    loadA(0); loadH(0);
    stsA(0); stsH(0);
    __syncthreads();
    int cur = 0;
    for (int kc = 0; kc < CN; kc += 16) {
        const bool has = (kc + 16 < CN);
        if (has) { loadA(kc + 16); loadH(kc + 16); }
        tile_compute_128(As[cur], Hs[cur], acc, n_off, f_off, g, t);
        if (has) { stsA(cur ^ 1); stsH(cur ^ 1); }
        __syncthreads();
        cur ^= 1;
    }

    const float* xold = (h == 0) ? xoldA : xoldB;
    float* xout = (h == 0) ? xoutA : xoutB;
    const float* degp = g_degs + (size_t)hb*CN;
    #pragma unroll
    for (int fn = 0; fn < 2; fn++)
        #pragma unroll
        for (int half = 0; half < 2; half++) {
            int n = n0 + n_off + fn*16 + g + half*8;
            float dinv = 1.0f / degp[n];
            #pragma unroll
            for (int fm = 0; fm < 8; fm++) {
                int f = f0 + f_off + fm*8 + 2*t;
                size_t idx = (size_t)b*CN*CD + (size_t)n*CD + f;
                float v0 = acc[fn][fm][half*2]   * dinv + bias[f];
                float v1 = acc[fn][fm][half*2+1] * dinv + bias[f+1];
                float2 o;
                o.x = xold[idx]     + fmaxf(v0, 0.0f);
                o.y = xold[idx + 1] + fmaxf(v1, 0.0f);
                *(float2*)&xout[idx] = o;
            }
        }
}

// =====================================================================
extern "C" void kernel_launch(void* const* d_in, const int* in_sizes, int n_in,
                              void* d_out, int out_size)
{
    (void)in_sizes; (void)n_in; (void)out_size;
    const float* X   = (const float*)d_in[0];
    const int*   adj = (const int*)d_in[1];
    const float* Wq  = (const float*)d_in[2];
    const float* bq  = (const float*)d_in[3];
    const float* Wk  = (const float*)d_in[4];
    const float* bk  = (const float*)d_in[5];
    const float* gW  = (const float*)d_in[6];
    const float* gb  = (const float*)d_in[7];
    const float* aW  = (const float*)d_in[8];
    const float* ab  = (const float*)d_in[9];

    float* out = (float*)d_out;                      // (B,N,D)
    float* ga  = out + (size_t)CB*CN*CD;             // (H,B,N,N)

    float *qb, *kb, *h1a, *h1b, *x0, *x1, *dg;
    cudaGetSymbolAddress((void**)&qb,  g_q);
    cudaGetSymbolAddress((void**)&kb,  g_k);
    cudaGetSymbolAddress((void**)&h1a, g_h1a);
    cudaGetSymbolAddress((void**)&h1b, g_h1b);
    cudaGetSymbolAddress((void**)&x0,  g_x0);
    cudaGetSymbolAddress((void**)&x1,  g_x1);
    cudaGetSymbolAddress((void**)&dg,  g_degs);

    // Launch 1: 6 projections + iter-0 h1, all A = X, one batched launch (z=7)
    GemmJobs J1 = {};
    for (int e = 0; e < CE; e++) {
        J1.A0[2*e] = X;  J1.A1[2*e] = X;
        J1.W[2*e] = Wq + (size_t)e*CD*CD;  J1.bias[2*e] = bq + e*CD;
        J1.C[2*e] = qb + (size_t)e*CB*CN*CD;  J1.split[2*e] = 0;
        J1.A0[2*e+1] = X;  J1.A1[2*e+1] = X;
        J1.W[2*e+1] = Wk + (size_t)e*CD*CD;  J1.bias[2*e+1] = bk + e*CD;
        J1.C[2*e+1] = kb + (size_t)e*CB*CN*CD;  J1.split[2*e+1] = 0;
    }
    J1.A0[6] = X;  J1.A1[6] = X;  J1.W[6] = gW;  J1.bias[6] = nullptr;
    J1.C[6] = h1a;  J1.split[6] = 0;
    gemm_mma_kernel<<<dim3(2, 64, 7), 256>>>(J1, CD);

    // Scores -> graph_attention region, then softmax (+degs)
    scores_kernel<<<dim3(CN/64, CN/128, CB*CH), 256>>>(adj, ga);
    softmax_kernel<<<dim3(CN, CH*CB), 256>>>(ga, dg);

    // GCN iteration 0: both heads share h1a; one z=8 launch
    spmm_kernel<<<dim3(CD/128, CN/128, CH*CB), 256>>>(ga, h1a, h1a, X, X, x0, x1, gb, 0);

    // GCN iteration 1: both h1 gemms in one z=2 launch, then one z=8 spmm
    GemmJobs J2 = {};
    J2.A0[0] = x0;  J2.A1[0] = x0;  J2.W[0] = gW + (size_t)CD*CD;
    J2.bias[0] = nullptr;  J2.C[0] = h1a;  J2.split[0] = 0;
    J2.A0[1] = x1;  J2.A1[1] = x1;  J2.W[1] = gW + (size_t)CD*CD;
    J2.bias[1] = nullptr;  J2.C[1] = h1b;  J2.split[1] = 0;
    gemm_mma_kernel<<<dim3(2, 64, 2), 256>>>(J2, CD);
    spmm_kernel<<<dim3(CD/128, CN/128, CH*CB), 256>>>(ga, h1a, h1b, x0, x1, x0, x1, gb + CD, 0);

    // Aggregation: out = concat(x0, x1) @ agg_W + agg_b (split-K)
    GemmJobs J3 = {};
    J3.A0[0] = x0;  J3.A1[0] = x1;  J3.W[0] = aW;  J3.bias[0] = ab;
    J3.C[0] = out;  J3.split[0] = 1;
    gemm_mma_kernel<<<dim3(2, 64, 1), 256>>>(J3, 2*CD);
}

// round 16
// speedup vs baseline: 1.9276x; 1.0691x over previous
#include <cuda_runtime.h>
#include <cuda_fp16.h>
#include <cstdint>

#define CB 4
#define CN 2048
#define CD 256
#define CE 3
#define CH 2
#define CDK 128
#define NEGF -1000000000.0f
#define QK_PAD 20
#define HP 20          // fp16 tile row stride (halfs): 16 data + 4 pad
#define MAXJ 8

// ---- scratch (static device globals; no allocation allowed) ----
__device__ __half g_qh[(size_t)CE*CB*CN*CD];   // Q projections, fp16 hi
__device__ __half g_ql[(size_t)CE*CB*CN*CD];   // Q projections, fp16 lo
__device__ __half g_kh[(size_t)CE*CB*CN*CD];   // K projections, fp16 hi
__device__ __half g_kl[(size_t)CE*CB*CN*CD];   // K projections, fp16 lo
__device__ __half g_ah[(size_t)CH*CB*CN*CN];   // attn fp16 hi (normalized)
__device__ __half g_al[(size_t)CH*CB*CN*CN];   // attn fp16 lo
__device__ __half g_h1ath[(size_t)CB*CD*CN];   // h1a transposed [b][f][m] hi
__device__ __half g_h1atl[(size_t)CB*CD*CN];   // h1a transposed lo
__device__ __half g_h1bth[(size_t)CB*CD*CN];   // h1b transposed hi
__device__ __half g_h1btl[(size_t)CB*CD*CN];   // h1b transposed lo
__device__ float g_h1a[(size_t)CB*CN*CD];      // GCN h1 buffer (f32)
__device__ float g_h1b[(size_t)CB*CN*CD];
__device__ float g_x0[(size_t)CB*CN*CD];       // head-0 node state
__device__ float g_x1[(size_t)CB*CN*CD];       // head-1 node state
__device__ float g_degs[(size_t)CH*CB*CN];     // row sums of attn (degs)

// ---------------------------------------------------------------------
// MMA helpers.
// tf32 m16n8k8 split (for the dense projection GEMMs, unchanged).
// fp16 m16n8k16 3-term split (scores + spmm): hi/lo precomputed by the
// producer, so the inner loop has ZERO split ALU and half the MMAs.
// ---------------------------------------------------------------------
__device__ __forceinline__ float tf32_hi(float x) {
    return __uint_as_float(__float_as_uint(x) & 0xFFFFE000u);
}

__device__ __forceinline__ void mma_tf32(float* c, const float* a, const float* b) {
    asm volatile(
        "mma.sync.aligned.m16n8k8.row.col.f32.tf32.tf32.f32 "
        "{%0,%1,%2,%3}, {%4,%5,%6,%7}, {%8,%9}, {%0,%1,%2,%3};\n"
        : "+f"(c[0]), "+f"(c[1]), "+f"(c[2]), "+f"(c[3])
        : "r"(__float_as_uint(a[0])), "r"(__float_as_uint(a[1])),
          "r"(__float_as_uint(a[2])), "r"(__float_as_uint(a[3])),
          "r"(__float_as_uint(b[0])), "r"(__float_as_uint(b[1])));
}

__device__ __forceinline__ void mma_f16(float* c, const uint32_t* a, const uint32_t* b) {
    asm volatile(
        "mma.sync.aligned.m16n8k16.row.col.f32.f16.f16.f32 "
        "{%0,%1,%2,%3}, {%4,%5,%6,%7}, {%8,%9}, {%0,%1,%2,%3};\n"
        : "+f"(c[0]), "+f"(c[1]), "+f"(c[2]), "+f"(c[3])
        : "r"(a[0]), "r"(a[1]), "r"(a[2]), "r"(a[3]),
          "r"(b[0]), "r"(b[1]));
}

__device__ __forceinline__ void split_h(float v, __half& h, __half& l) {
    h = __float2half_rn(v);
    l = __float2half_rn(v - __half2float(h));
}

// ---- tf32 tile compute for the projection GEMM (unchanged) ----
__device__ __forceinline__ void tile_compute_128(
    const float (&As)[128][QK_PAD], const float (&Hs)[16][136],
    float (&acc)[2][8][4], int m_off, int n_off, int g, int t)
{
    #pragma unroll
    for (int ks = 0; ks < 16; ks += 8) {
        float ah[2][4], al[2][4];
        #pragma unroll
        for (int fn = 0; fn < 2; fn++) {
            int r0 = m_off + fn*16 + g;
            float a0 = As[r0    ][ks + t];
            float a1 = As[r0 + 8][ks + t];
            float a2 = As[r0    ][ks + t + 4];
            float a3 = As[r0 + 8][ks + t + 4];
            ah[fn][0]=tf32_hi(a0); al[fn][0]=a0-ah[fn][0];
            ah[fn][1]=tf32_hi(a1); al[fn][1]=a1-ah[fn][1];
            ah[fn][2]=tf32_hi(a2); al[fn][2]=a2-ah[fn][2];
            ah[fn][3]=tf32_hi(a3); al[fn][3]=a3-ah[fn][3];
        }
        #pragma unroll
        for (int fm = 0; fm < 8; fm++) {
            int c = n_off + fm*8 + g;
            float b0 = Hs[ks + t    ][c];
            float b1 = Hs[ks + t + 4][c];
            float bh[2], bl[2];
            bh[0]=tf32_hi(b0); bl[0]=b0-bh[0];
            bh[1]=tf32_hi(b1); bl[1]=b1-bh[1];
            #pragma unroll
            for (int fn = 0; fn < 2; fn++) {
                mma_tf32(acc[fn][fm], ah[fn], bh);
                mma_tf32(acc[fn][fm], ah[fn], bl);
                mma_tf32(acc[fn][fm], al[fn], bh);
            }
        }
    }
}

// =====================================================================
// Batched tf32-split GEMM, double-buffered. Per z-job:
// C f32 write if C != null; fp16 hi/lo plane write if Chi != null.
// =====================================================================
struct GemmJobs {
    const float* A0[MAXJ];
    const float* A1[MAXJ];
    const float* W[MAXJ];
    const float* bias[MAXJ];
    float* C[MAXJ];
    __half* Chi[MAXJ];
    __half* Clo[MAXJ];
    int split[MAXJ];
};

__global__ void __launch_bounds__(256, 2) gemm_mma_kernel(GemmJobs jobs, int K)
{
    __shared__ float As[2][128][QK_PAD];
    __shared__ float Ws[2][16][136];
    const int tid = threadIdx.x;
    const int wid = tid >> 5;
    const int lane = tid & 31;
    const int g = lane >> 2;
    const int t = lane & 3;
    const int m_off = (wid & 3) * 32;
    const int n_off = (wid >> 2) * 64;
    const int z = blockIdx.z;
    const float* A0 = jobs.A0[z];
    const float* A1 = jobs.A1[z];
    const float* W  = jobs.W[z];
    const float* bias = jobs.bias[z];
    float* C = jobs.C[z];
    __half* Chi = jobs.Chi[z];
    __half* Clo = jobs.Clo[z];
    const int split = jobs.split[z];
    const int bn0 = blockIdx.x * 128;
    const int bm0 = blockIdx.y * 128;

    float acc[2][8][4];
    #pragma unroll
    for (int i = 0; i < 2; i++)
        #pragma unroll
        for (int j = 0; j < 8; j++)
            #pragma unroll
            for (int c = 0; c < 4; c++) acc[i][j][c] = 0.0f;

    float4 pa[2], pw[2];
    auto loadA = [&](int kc) {
        #pragma unroll
        for (int it = 0; it < 2; it++) {
            int id = tid + it * 256;
            int r = id >> 2;
            int k4 = id & 3;
            int gk = kc + k4 * 4;
            const float* base = A0; int col = gk;
            if (split && gk >= 256) { base = A1; col = gk - 256; }
            pa[it] = *(const float4*)(base + (size_t)(bm0 + r) * 256 + col);
        }
    };
    auto loadW = [&](int kc) {
        #pragma unroll
        for (int it = 0; it < 2; it++) {
            int id = tid + it * 256;
            int f4 = id & 31;
            int k = id >> 5;
            pw[it] = *(const float4*)(W + (size_t)(kc + k) * 256 + bn0 + f4 * 4);
        }
    };
    auto stsA = [&](int buf) {
        #pragma unroll
        for (int it = 0; it < 2; it++) {
            int id = tid + it * 256;
            int r = id >> 2, k4 = id & 3;
            *(float4*)&As[buf][r][k4*4] = pa[it];
        }
    };
    auto stsW = [&](int buf) {
        #pragma unroll
        for (int it = 0; it < 2; it++) {
            int id = tid + it * 256;
            int f4 = id & 31, k = id >> 5;
            *(float4*)&Ws[buf][k][f4*4] = pw[it];
        }
    };

    loadA(0); loadW(0);
    stsA(0); stsW(0);
    __syncthreads();
    int cur = 0;
    for (int kc = 0; kc < K; kc += 16) {
        const bool has = (kc + 16 < K);
        if (has) { loadA(kc + 16); loadW(kc + 16); }
        tile_compute_128(As[cur], Ws[cur], acc, m_off, n_off, g, t);
        if (has) { stsA(cur ^ 1); stsW(cur ^ 1); }
        __syncthreads();
        cur ^= 1;
    }

    #pragma unroll
    for (int fn = 0; fn < 2; fn++)
        #pragma unroll
        for (int half = 0; half < 2; half++) {
            int m = bm0 + m_off + fn*16 + g + half*8;
            #pragma unroll
            for (int fm = 0; fm < 8; fm++) {
                int n = bn0 + n_off + fm*8 + 2*t;
                float bv0 = bias ? bias[n]     : 0.0f;
                float bv1 = bias ? bias[n + 1] : 0.0f;
                float v0 = acc[fn][fm][half*2]   + bv0;
                float v1 = acc[fn][fm][half*2+1] + bv1;
                if (C) {
                    float2 o; o.x = v0; o.y = v1;
                    *(float2*)&C[(size_t)m*256 + n] = o;
                }
                if (Chi) {
                    __half h0, l0, h1v, l1;
                    split_h(v0, h0, l0);
                    split_h(v1, h1v, l1);
                    *(__half2*)&Chi[(size_t)m*256 + n] = __halves2half2(h0, h1v);
                    *(__half2*)&Clo[(size_t)m*256 + n] = __halves2half2(l0, l1);
                }
            }
        }
}

// =====================================================================
// Transpose + fp16-split convert: src f32 [b][m=2048][f=256] ->
// dsth/dstl fp16 [b][f=256][m=2048].
// =====================================================================
__global__ void __launch_bounds__(256) h1_transpose_kernel(
    const float* __restrict__ src, __half* __restrict__ dsth, __half* __restrict__ dstl)
{
    __shared__ float T[32][33];
    const int b = blockIdx.z;
    const int m0 = blockIdx.x * 32;
    const int f0 = blockIdx.y * 32;
    const int tx = threadIdx.x & 31;
    const int ty = threadIdx.x >> 5;   // 0..7
    const float* s = src + (size_t)b*CN*CD;
    #pragma unroll
    for (int i = 0; i < 4; i++) {
        int m = ty + i*8;
        T[m][tx] = s[(size_t)(m0 + m)*CD + f0 + tx];
    }
    __syncthreads();
    __half* dh = dsth + (size_t)b*CD*CN;
    __half* dl = dstl + (size_t)b*CD*CN;
    #pragma unroll
    for (int i = 0; i < 4; i++) {
        int f = ty + i*8;
        float v = T[tx][f];
        __half h, l;
        split_h(v, h, l);
        dh[(size_t)(f0 + f)*CN + m0 + tx] = h;
        dl[(size_t)(f0 + f)*CN + m0 + tx] = l;
    }
}

// =====================================================================
// Edge-typed attention scores, fp16 m16n8k16 3-term. Per-edge passes
// with running selection tile. Block 128(n) x 64(m); 8 warps of 32x32.
// =====================================================================
__global__ void __launch_bounds__(256, 2) scores_kernel(
    const int* __restrict__ adj, float* __restrict__ ga)
{
    __shared__ __align__(16) __half QsH[2][128][HP];
    __shared__ __align__(16) __half QsL[2][128][HP];
    __shared__ __align__(16) __half KsH[2][64][HP];
    __shared__ __align__(16) __half KsL[2][64][HP];
    const int tid = threadIdx.x;
    const int wid = tid >> 5;
    const int lane = tid & 31;
    const int g = lane >> 2;
    const int t = lane & 3;
    const int n_off = (wid & 3) * 32;
    const int m_off = (wid >> 2) * 32;
    const int bh = blockIdx.z;
    const int b = bh >> 1;
    const int h = bh & 1;
    const int m0 = blockIdx.x * 64;
    const int n0 = blockIdx.y * 128;
    const int* adjb = adj + (size_t)b*CN*CN;
    const float scale = 0.088388347648318447f;  // 1/sqrt(128)

    float merged[2][4][4];
    #pragma unroll
    for (int i = 0; i < 2; i++)
        #pragma unroll
        for (int j = 0; j < 4; j++)
            #pragma unroll
            for (int c = 0; c < 4; c++) merged[i][j][c] = 0.0f;

    for (int e = 0; e < CE; e++) {
        const size_t qoff = ((size_t)(e*CB + b)*CN + n0)*CD + h*CDK;
        const size_t koff = ((size_t)(e*CB + b)*CN + m0)*CD + h*CDK;
        const __half* Qh = g_qh + qoff;
        const __half* Ql = g_ql + qoff;
        const __half* Kh = g_kh + koff;
        const __half* Kl = g_kl + koff;

        float acc[2][4][4];
        #pragma unroll
        for (int i = 0; i < 2; i++)
            #pragma unroll
            for (int j = 0; j < 4; j++)
                #pragma unroll
                for (int c = 0; c < 4; c++) acc[i][j][c] = 0.0f;

        uint4 pqh, pql;
        uint2 pkh, pkl;
        const int qrow = tid >> 1, qseg = tid & 1;          // 128 rows x 2 segs
        const int krow = tid >> 2, kq4 = tid & 3;           // 64 rows x 4 quads
        auto loadQ = [&](int kc) {
            size_t p = (size_t)qrow*CD + kc + qseg*8;
            pqh = *(const uint4*)(Qh + p);
            pql = *(const uint4*)(Ql + p);
        };
        auto loadK = [&](int kc) {
            size_t p = (size_t)krow*CD + kc + kq4*4;
            pkh = *(const uint2*)(Kh + p);
            pkl = *(const uint2*)(Kl + p);
        };
        auto stsQ = [&](int buf) {
            *(uint2*)&QsH[buf][qrow][qseg*8]     = make_uint2(pqh.x, pqh.y);
            *(uint2*)&QsH[buf][qrow][qseg*8 + 4] = make_uint2(pqh.z, pqh.w);
            *(uint2*)&QsL[buf][qrow][qseg*8]     = make_uint2(pql.x, pql.y);
            *(uint2*)&QsL[buf][qrow][qseg*8 + 4] = make_uint2(pql.z, pql.w);
        };
        auto stsK = [&](int buf) {
            *(uint2*)&KsH[buf][krow][kq4*4] = pkh;
            *(uint2*)&KsL[buf][krow][kq4*4] = pkl;
        };

        loadQ(0); loadK(0);
        stsQ(0); stsK(0);
        __syncthreads();
        int cur = 0;
        for (int kc = 0; kc < CDK; kc += 16) {
            const bool has = (kc + 16 < CDK);
            if (has) { loadQ(kc + 16); loadK(kc + 16); }
            uint32_t ah4[2][4], al4[2][4];
            #pragma unroll
            for (int fn = 0; fn < 2; fn++) {
                int r0 = n_off + fn*16 + g;
                ah4[fn][0] = *(const uint32_t*)&QsH[cur][r0    ][2*t];
                ah4[fn][1] = *(const uint32_t*)&QsH[cur][r0 + 8][2*t];
                ah4[fn][2] = *(const uint32_t*)&QsH[cur][r0    ][2*t + 8];
                ah4[fn][3] = *(const uint32_t*)&QsH[cur][r0 + 8][2*t + 8];
                al4[fn][0] = *(const uint32_t*)&QsL[cur][r0    ][2*t];
                al4[fn][1] = *(const uint32_t*)&QsL[cur][r0 + 8][2*t];
                al4[fn][2] = *(const uint32_t*)&QsL[cur][r0    ][2*t + 8];
                al4[fn][3] = *(const uint32_t*)&QsL[cur][r0 + 8][2*t + 8];
            }
            #pragma unroll
            for (int fm = 0; fm < 4; fm++) {
                int rk = m_off + fm*8 + g;
                uint32_t bh2[2], bl2[2];
                bh2[0] = *(const uint32_t*)&KsH[cur][rk][2*t];
                bh2[1] = *(const uint32_t*)&KsH[cur][rk][2*t + 8];
                bl2[0] = *(const uint32_t*)&KsL[cur][rk][2*t];
                bl2[1] = *(const uint32_t*)&KsL[cur][rk][2*t + 8];
                #pragma unroll
                for (int fn = 0; fn < 2; fn++) {
                    mma_f16(acc[fn][fm], ah4[fn], bh2);
                    mma_f16(acc[fn][fm], ah4[fn], bl2);
                    mma_f16(acc[fn][fm], al4[fn], bh2);
                }
            }
            if (has) { stsQ(cur ^ 1); stsK(cur ^ 1); }
            __syncthreads();
            cur ^= 1;
        }

        // merge this edge's scores where adj == e+1
        #pragma unroll
        for (int fn = 0; fn < 2; fn++)
            #pragma unroll
            for (int fm = 0; fm < 4; fm++)
                #pragma unroll
                for (int half = 0; half < 2; half++) {
                    int n = n0 + n_off + fn*16 + g + half*8;
                    int m = m0 + m_off + fm*8 + 2*t;
                    int2 av = *(const int2*)&adjb[(size_t)n*CN + m];
                    if (av.x == e + 1) merged[fn][fm][half*2]   = acc[fn][fm][half*2]   * scale;
                    if (av.y == e + 1) merged[fn][fm][half*2+1] = acc[fn][fm][half*2+1] * scale;
                }
    }

    float* gout = ga + (size_t)(h*CB + b)*CN*CN;
    #pragma unroll
    for (int fn = 0; fn < 2; fn++)
        #pragma unroll
        for (int fm = 0; fm < 4; fm++)
            #pragma unroll
            for (int half = 0; half < 2; half++) {
                int n = n0 + n_off + fn*16 + g + half*8;
                int m = m0 + m_off + fm*8 + 2*t;
                float r0 = merged[fn][fm][half*2];
                float r1 = merged[fn][fm][half*2+1];
                float2 o;
                o.x = (r0 == 0.0f) ? NEGF : r0;
                o.y = (r1 == 0.0f) ? NEGF : r1;
                *(float2*)&gout[(size_t)n*CN + m] = o;
            }
}

// =====================================================================
// Row softmax over 2048 + degs; also emits attn fp16 hi/lo planes.
// Thread handles 8 CONTIGUOUS elements (vectorized loads + plane writes).
// =====================================================================
__global__ void __launch_bounds__(256) softmax_kernel(
    float* __restrict__ ga, __half* __restrict__ ah, __half* __restrict__ al,
    float* __restrict__ degs)
{
    const size_t roff = ((size_t)blockIdx.y * CN + blockIdx.x) * CN;
    float* p = ga + roff;
    const int tid = threadIdx.x;
    float v[8];
    float4 va = *(const float4*)(p + tid*8);
    float4 vb = *(const float4*)(p + tid*8 + 4);
    v[0]=va.x; v[1]=va.y; v[2]=va.z; v[3]=va.w;
    v[4]=vb.x; v[5]=vb.y; v[6]=vb.z; v[7]=vb.w;
    float lmax = v[0];
    #pragma unroll
    for (int i = 1; i < 8; i++) lmax = fmaxf(lmax, v[i]);
    #pragma unroll
    for (int o = 16; o; o >>= 1) lmax = fmaxf(lmax, __shfl_xor_sync(0xffffffffu, lmax, o));
    __shared__ float red[8];
    if ((tid & 31) == 0) red[tid >> 5] = lmax;
    __syncthreads();
    float rmax = red[0];
    #pragma unroll
    for (int i = 1; i < 8; i++) rmax = fmaxf(rmax, red[i]);
    float lsum = 0.0f;
    #pragma unroll
    for (int i = 0; i < 8; i++) { v[i] = __expf(v[i] - rmax); lsum += v[i]; }
    #pragma unroll
    for (int o = 16; o; o >>= 1) lsum += __shfl_xor_sync(0xffffffffu, lsum, o);
    __syncthreads();
    __shared__ float red2[8];
    if ((tid & 31) == 0) red2[tid >> 5] = lsum;
    __syncthreads();
    float rsum = 0.0f;
    #pragma unroll
    for (int i = 0; i < 8; i++) rsum += red2[i];
    float rinv = 1.0f / rsum;
    float w[8];
    float lw = 0.0f;
    #pragma unroll
    for (int i = 0; i < 8; i++) { w[i] = v[i]*rinv; lw += w[i]; }
    float4 oa, ob;
    oa.x=w[0]; oa.y=w[1]; oa.z=w[2]; oa.w=w[3];
    ob.x=w[4]; ob.y=w[5]; ob.z=w[6]; ob.w=w[7];
    *(float4*)(p + tid*8)     = oa;
    *(float4*)(p + tid*8 + 4) = ob;
    // fp16 hi/lo planes
    __half2 hh[4], ll[4];
    #pragma unroll
    for (int i = 0; i < 4; i++) {
        __half h0, l0, h1v, l1;
        split_h(w[2*i],   h0, l0);
        split_h(w[2*i+1], h1v, l1);
        hh[i] = __halves2half2(h0, h1v);
        ll[i] = __halves2half2(l0, l1);
    }
    *(uint4*)(ah + roff + tid*8) = *(uint4*)hh;
    *(uint4*)(al + roff + tid*8) = *(uint4*)ll;

    #pragma unroll
    for (int o = 16; o; o >>= 1) lw += __shfl_xor_sync(0xffffffffu, lw, o);
    __shared__ float red3[8];
    if ((tid & 31) == 0) red3[tid >> 5] = lw;
    __syncthreads();
    if (tid == 0) {
        float s = 0.0f;
        #pragma unroll
        for (int i = 0; i < 8; i++) s += red3[i];
        degs[(size_t)blockIdx.y*CN + blockIdx.x] = s;
    }
}

// =====================================================================
// GCN aggregation, fp16 m16n8k16 3-term, double-buffered.
// C = attn(hb) @ h1; epilogue x_out = x_old + relu(C/deg + gcn_b).
// A from attn planes [hb][n][m]; B from transposed h1 planes [b][f][m].
// =====================================================================
__global__ void __launch_bounds__(256, 2) spmm_kernel(
    const __half* __restrict__ Ah, const __half* __restrict__ Al,
    const __half* __restrict__ H0h, const __half* __restrict__ H0l,
    const __half* __restrict__ H1h, const __half* __restrict__ H1l,
    const float* __restrict__ xoldA, const float* __restrict__ xoldB,
    float* __restrict__ xoutA, float* __restrict__ xoutB,
    const float* __restrict__ bias, int hb0)
{
    __shared__ __align__(16) __half AsH[2][128][HP];
    __shared__ __align__(16) __half AsL[2][128][HP];
    __shared__ __align__(16) __half HsH[2][128][HP];
    __shared__ __align__(16) __half HsL[2][128][HP];
    const int tid = threadIdx.x;
    const int wid = tid >> 5;
    const int lane = tid & 31;
    const int g = lane >> 2;
    const int t = lane & 3;
    const int n_off = (wid & 3) * 32;
    const int f_off = (wid >> 2) * 64;
    const int hb = hb0 + blockIdx.z;
    const int h = hb / CB;
    const int b = hb % CB;
    const int f0 = blockIdx.x * 128;
    const int n0 = blockIdx.y * 128;
    const __half* Abh = Ah + (size_t)hb*CN*CN;
    const __half* Abl = Al + (size_t)hb*CN*CN;
    const __half* Hbh = ((h == 0) ? H0h : H1h) + (size_t)b*CD*CN;
    const __half* Hbl = ((h == 0) ? H0l : H1l) + (size_t)b*CD*CN;

    float acc[2][8][4];
    #pragma unroll
    for (int i = 0; i < 2; i++)
        #pragma unroll
        for (int j = 0; j < 8; j++)
            #pragma unroll
            for (int c = 0; c < 4; c++) acc[i][j][c] = 0.0f;

    uint4 pah, pal, phh, phl;
    const int row = tid >> 1, seg = tid & 1;   // 128 rows x 2 segs of 8 halfs
    auto loadA = [&](int kc) {
        size_t p = (size_t)(n0 + row)*CN + kc + seg*8;
        pah = *(const uint4*)(Abh + p);
        pal = *(const uint4*)(Abl + p);
    };
    auto loadH = [&](int kc) {
        size_t p = (size_t)(f0 + row)*CN + kc + seg*8;
        phh = *(const uint4*)(Hbh + p);
        phl = *(const uint4*)(Hbl + p);
    };
    auto stsA = [&](int buf) {
        *(uint2*)&AsH[buf][row][seg*8]     = make_uint2(pah.x, pah.y);
        *(uint2*)&AsH[buf][row][seg*8 + 4] = make_uint2(pah.z, pah.w);
        *(uint2*)&AsL[buf][row][seg*8]     = make_uint2(pal.x, pal.y);
        *(uint2*)&AsL[buf][row][seg*8 + 4] = make_uint2(pal.z, pal.w);
    };
    auto stsH = [&](int buf) {
        *(uint2*)&HsH[buf][row][seg*8]     = make_uint2(phh.x, phh.y);
        *(uint2*)&HsH[buf][row][seg*8 + 4] = make_uint2(phh.z, phh.w);
        *(uint2*)&HsL[buf][row][seg*8]     = make_uint2(phl.x, phl.y);
        *(uint2*)&HsL[buf][row][seg*8 + 4] = make_uint2(phl.z, phl.w);
    };

    loadA(0); loadH(0);
    stsA(0); stsH(0);
    __syncthreads();
    int cur = 0;
    for (int kc = 0; kc < CN; kc += 16) {
        const bool has = (kc + 16 < CN);
        if (has) { loadA(kc + 16); loadH(kc + 16); }
        uint32_t ah4[2][4], al4[2][4];
        #pragma unroll
        for (int fn = 0; fn < 2; fn++) {
            int r0 = n_off + fn*16 + g;
            ah4[fn][0] = *(const uint32_t*)&AsH[cur][r0    ][2*t];
            ah4[fn][1] = *(const uint32_t*)&AsH[cur][r0 + 8][2*t];
            ah4[fn][2] = *(const uint32_t*)&AsH[cur][r0    ][2*t + 8];
            ah4[fn][3] = *(const uint32_t*)&AsH[cur][r0 + 8][2*t + 8];
            al4[fn][0] = *(const uint32_t*)&AsL[cur][r0    ][2*t];
            al4[fn][1] = *(const uint32_t*)&AsL[cur][r0 + 8][2*t];
            al4[fn][2] = *(const uint32_t*)&AsL[cur][r0    ][2*t + 8];
            al4[fn][3] = *(const uint32_t*)&AsL[cur][r0 + 8][2*t + 8];
        }
        #pragma unroll
        for (int fm = 0; fm < 8; fm++) {
            int rk = f_off + fm*8 + g;
            uint32_t bh2[2], bl2[2];
            bh2[0] = *(const uint32_t*)&HsH[cur][rk][2*t];
            bh2[1] = *(const uint32_t*)&HsH[cur][rk][2*t + 8];
            bl2[0] = *(const uint32_t*)&HsL[cur][rk][2*t];
            bl2[1] = *(const uint32_t*)&HsL[cur][rk][2*t + 8];
            #pragma unroll
            for (int fn = 0; fn < 2; fn++) {
                mma_f16(acc[fn][fm], ah4[fn], bh2);
                mma_f16(acc[fn][fm], ah4[fn], bl2);
                mma_f16(acc[fn][fm], al4[fn], bh2);
            }
        }
        if (has) { stsA(cur ^ 1); stsH(cur ^ 1); }
        __syncthreads();
        cur ^= 1;
    }

    const float* xold = (h == 0) ? xoldA : xoldB;
    float* xout = (h == 0) ? xoutA : xoutB;
    const float* degp = g_degs + (size_t)hb*CN;
    #pragma unroll
    for (int fn = 0; fn < 2; fn++)
        #pragma unroll
        for (int half = 0; half < 2; half++) {
            int n = n0 + n_off + fn*16 + g + half*8;
            float dinv = 1.0f / degp[n];
            #pragma unroll
            for (int fm = 0; fm < 8; fm++) {
                int f = f0 + f_off + fm*8 + 2*t;
                size_t idx = (size_t)b*CN*CD + (size_t)n*CD + f;
                float v0 = acc[fn][fm][half*2]   * dinv + bias[f];
                float v1 = acc[fn][fm][half*2+1] * dinv + bias[f+1];
                float2 o;
                o.x = xold[idx]     + fmaxf(v0, 0.0f);
                o.y = xold[idx + 1] + fmaxf(v1, 0.0f);
                *(float2*)&xout[idx] = o;
            }
        }
}

// =====================================================================
extern "C" void kernel_launch(void* const* d_in, const int* in_sizes, int n_in,
                              void* d_out, int out_size)
{
    (void)in_sizes; (void)n_in; (void)out_size;
    const float* X   = (const float*)d_in[0];
    const int*   adj = (const int*)d_in[1];
    const float* Wq  = (const float*)d_in[2];
    const float* bq  = (const float*)d_in[3];
    const float* Wk  = (const float*)d_in[4];
    const float* bk  = (const float*)d_in[5];
    const float* gW  = (const float*)d_in[6];
    const float* gb  = (const float*)d_in[7];
    const float* aW  = (const float*)d_in[8];
    const float* ab  = (const float*)d_in[9];

    float* out = (float*)d_out;                      // (B,N,D)
    float* ga  = out + (size_t)CB*CN*CD;             // (H,B,N,N)

    __half *qh, *ql, *kh, *kl, *ath, *atl, *h1ath, *h1atl, *h1bth, *h1btl;
    float *h1a, *h1b, *x0, *x1, *dg;
    cudaGetSymbolAddress((void**)&qh,    g_qh);
    cudaGetSymbolAddress((void**)&ql,    g_ql);
    cudaGetSymbolAddress((void**)&kh,    g_kh);
    cudaGetSymbolAddress((void**)&kl,    g_kl);
    cudaGetSymbolAddress((void**)&ath,   g_ah);
    cudaGetSymbolAddress((void**)&atl,   g_al);
    cudaGetSymbolAddress((void**)&h1ath, g_h1ath);
    cudaGetSymbolAddress((void**)&h1atl, g_h1atl);
    cudaGetSymbolAddress((void**)&h1bth, g_h1bth);
    cudaGetSymbolAddress((void**)&h1btl, g_h1btl);
    cudaGetSymbolAddress((void**)&h1a,   g_h1a);
    cudaGetSymbolAddress((void**)&h1b,   g_h1b);
    cudaGetSymbolAddress((void**)&x0,    g_x0);
    cudaGetSymbolAddress((void**)&x1,    g_x1);
    cudaGetSymbolAddress((void**)&dg,    g_degs);

    // Launch 1: 6 projections (fp16-plane outputs) + iter-0 h1 (f32), z=7
    GemmJobs J1 = {};
    for (int e = 0; e < CE; e++) {
        size_t po = (size_t)e*CB*CN*CD;
        J1.A0[2*e] = X;  J1.A1[2*e] = X;
        J1.W[2*e] = Wq + (size_t)e*CD*CD;  J1.bias[2*e] = bq + e*CD;
        J1.C[2*e] = nullptr;  J1.Chi[2*e] = qh + po;  J1.Clo[2*e] = ql + po;
        J1.split[2*e] = 0;
        J1.A0[2*e+1] = X;  J1.A1[2*e+1] = X;
        J1.W[2*e+1] = Wk + (size_t)e*CD*CD;  J1.bias[2*e+1] = bk + e*CD;
        J1.C[2*e+1] = nullptr;  J1.Chi[2*e+1] = kh + po;  J1.Clo[2*e+1] = kl + po;
        J1.split[2*e+1] = 0;
    }
    J1.A0[6] = X;  J1.A1[6] = X;  J1.W[6] = gW;  J1.bias[6] = nullptr;
    J1.C[6] = h1a;  J1.Chi[6] = nullptr;  J1.Clo[6] = nullptr;  J1.split[6] = 0;
    gemm_mma_kernel<<<dim3(2, 64, 7), 256>>>(J1, CD);

    // Transpose-convert h1a for iter-0 spmm
    h1_transpose_kernel<<<dim3(CN/32, CD/32, CB), 256>>>(h1a, h1ath, h1atl);

    // Scores -> ga, then softmax (+attn planes, degs)
    scores_kernel<<<dim3(CN/64, CN/128, CB*CH), 256>>>(adj, ga);
    softmax_kernel<<<dim3(CN, CH*CB), 256>>>(ga, ath, atl, dg);

    // GCN iteration 0: both heads share h1a planes; one z=8 launch
    spmm_kernel<<<dim3(CD/128, CN/128, CH*CB), 256>>>(
        ath, atl, h1ath, h1atl, h1ath, h1atl, X, X, x0, x1, gb, 0);

    // GCN iteration 1: both h1 gemms (f32), transpose both, one z=8 spmm
    GemmJobs J2 = {};
    J2.A0[0] = x0;  J2.A1[0] = x0;  J2.W[0] = gW + (size_t)CD*CD;
    J2.bias[0] = nullptr;  J2.C[0] = h1a;  J2.Chi[0] = nullptr;  J2.Clo[0] = nullptr;
    J2.split[0] = 0;
    J2.A0[1] = x1;  J2.A1[1] = x1;  J2.W[1] = gW + (size_t)CD*CD;
    J2.bias[1] = nullptr;  J2.C[1] = h1b;  J2.Chi[1] = nullptr;  J2.Clo[1] = nullptr;
    J2.split[1] = 0;
    gemm_mma_kernel<<<dim3(2, 64, 2), 256>>>(J2, CD);
    h1_transpose_kernel<<<dim3(CN/32, CD/32, CB), 256>>>(h1a, h1ath, h1atl);
    h1_transpose_kernel<<<dim3(CN/32, CD/32, CB), 256>>>(h1b, h1bth, h1btl);
    spmm_kernel<<<dim3(CD/128, CN/128, CH*CB), 256>>>(
        ath, atl, h1ath, h1atl, h1bth, h1btl, x0, x1, x0, x1, gb + CD, 0);

    // Aggregation: out = concat(x0, x1) @ agg_W + agg_b (split-K, f32)
    GemmJobs J3 = {};
    J3.A0[0] = x0;  J3.A1[0] = x1;  J3.W[0] = aW;  J3.bias[0] = ab;
    J3.C[0] = out;  J3.Chi[0] = nullptr;  J3.Clo[0] = nullptr;  J3.split[0] = 1;
    gemm_mma_kernel<<<dim3(2, 64, 1), 256>>>(J3, 2*CD);
}